// round 1
// baseline (speedup 1.0000x reference)
#include <cuda_runtime.h>
#include <math.h>

// Problem constants
#define BB 4
#define NN 16384
#define CC 256
#define HH 8
#define KK 64
#define DD 32
#define BNTOT (BB*NN)   // 65536

// ---------------- scratch (device globals: allocation-free) ----------------
__device__ float g_S[BB*KK*CC];        // A^T X  (4*64*256)
__device__ float g_denom[BB*KK];       // sum_n A
__device__ float g_kc[BB*HH*KK*DD];    // pooled K  (B,H,K,D)
__device__ float g_vc[BB*HH*KK*DD];    // pooled V
__device__ float g_q[BNTOT*CC];        // Q = X Wq   (BN,256) == (B,N,H,D)
__device__ float g_x[BNTOT*CC];        // attention output (B,N,C)

// ---------------- zero scratch accumulators ----------------
__global__ void zero_kernel() {
    int i = blockIdx.x * blockDim.x + threadIdx.x;
    if (i < BB*KK*CC) g_S[i] = 0.0f;
    if (i < BB*KK)    g_denom[i] = 0.0f;
}

// ---------------- pooling: S[b,k,c] = sum_n A[b,n,k] * X[b,n,c]; denom ----------------
// grid = 256 blocks (b * 64 chunks of 256 rows), 256 threads.
// thread (k = tid&63, cg = tid>>6) accumulates 64 c-values in registers.
__global__ __launch_bounds__(256) void pool_kernel(const float* __restrict__ X,
                                                   const float* __restrict__ Ag) {
    __shared__ float xs[4][CC];
    __shared__ float as_[4][KK];
    int tid = threadIdx.x;
    int k  = tid & 63;
    int cg = tid >> 6;          // 0..3 (c group of 64)
    int blk = blockIdx.x;
    int b = blk >> 6;
    size_t rowbase = (size_t)b * NN + (size_t)(blk & 63) * 256;

    float acc[64];
#pragma unroll
    for (int j = 0; j < 64; j++) acc[j] = 0.0f;
    float dsum = 0.0f;

    for (int n0 = 0; n0 < 256; n0 += 4) {
        // cooperative load of 4 rows of X (4x256) and A (4x64)
        *(float4*)&xs[cg][k * 4] =
            *(const float4*)(X + (rowbase + n0 + cg) * CC + k * 4);
        as_[cg][k] = Ag[(rowbase + n0 + cg) * KK + k];
        __syncthreads();
#pragma unroll
        for (int u = 0; u < 4; u++) {
            float a = as_[u][k];
            if (cg == 0) dsum += a;
            const float4* xr = (const float4*)&xs[u][cg * 64];
#pragma unroll
            for (int j4 = 0; j4 < 16; j4++) {
                float4 xv = xr[j4];                     // warp-broadcast
                acc[j4*4+0] += a * xv.x;
                acc[j4*4+1] += a * xv.y;
                acc[j4*4+2] += a * xv.z;
                acc[j4*4+3] += a * xv.w;
            }
        }
        __syncthreads();
    }
    float* Sout = &g_S[(b * KK + k) * CC + cg * 64];
#pragma unroll
    for (int j = 0; j < 64; j++) atomicAdd(&Sout[j], acc[j]);
    if (cg == 0) atomicAdd(&g_denom[b * KK + k], dsum);
}

// ---------------- kc/vc: k_cluster[b,h,k,d] = (S[b,k,:] @ Wk[:, h*32+d]) / (denom+eps) ----
// grid = 256 (b*64 + k), 256 threads (t = h*32+d)
__global__ __launch_bounds__(256) void kcvc_kernel(const float* __restrict__ wqkv) {
    int bk = blockIdx.x;
    int b = bk >> 6;
    int k = bk & 63;
    int t = threadIdx.x;
    __shared__ float s_row[CC];
    s_row[t] = g_S[bk * CC + t];
    __syncthreads();
    float inv = 1.0f / (g_denom[bk] + 1e-8f);
    float ak = 0.0f, av = 0.0f;
#pragma unroll 8
    for (int c = 0; c < CC; c++) {
        float s = s_row[c];
        ak += s * wqkv[c * (3*CC) + CC  + t];   // Wk column h*32+d
        av += s * wqkv[c * (3*CC) + 2*CC + t];  // Wv column
    }
    int h = t >> 5, dd = t & 31;
    int o = ((b * HH + h) * KK + k) * DD + dd;
    g_kc[o] = ak * inv;
    g_vc[o] = av * inv;
}

// ---------------- generic 128x128x8 SGEMM, optional bias ----------------
__global__ __launch_bounds__(256) void sgemm_kernel(
    const float* __restrict__ Am, const float* __restrict__ Bm,
    const float* __restrict__ bias, float* __restrict__ Cm,
    int M, int Nc, int Kd, int lda, int ldb, int ldc) {
    __shared__ float As[8][128];
    __shared__ float Bs[8][128];
    int tid = threadIdx.x;
    int tx = tid & 15, ty = tid >> 4;
    int bx = blockIdx.x, by = blockIdx.y;

    float acc[8][8];
#pragma unroll
    for (int i = 0; i < 8; i++)
#pragma unroll
        for (int j = 0; j < 8; j++) acc[i][j] = 0.0f;

    int aRow = tid >> 1;
    int aCol = (tid & 1) * 4;
    int bRow = tid >> 5;
    int bCol = (tid & 31) * 4;
    const float* Ap = Am + (size_t)(bx * 128 + aRow) * lda + aCol;
    const float* Bp = Bm + (size_t)bRow * ldb + by * 128 + bCol;

    for (int k0 = 0; k0 < Kd; k0 += 8) {
        float4 avv = *(const float4*)(Ap + k0);
        As[aCol+0][aRow] = avv.x;
        As[aCol+1][aRow] = avv.y;
        As[aCol+2][aRow] = avv.z;
        As[aCol+3][aRow] = avv.w;
        *(float4*)&Bs[bRow][bCol] = *(const float4*)(Bp + (size_t)k0 * ldb);
        __syncthreads();
#pragma unroll
        for (int kk = 0; kk < 8; kk++) {
            float ra[8], rb[8];
            *(float4*)&ra[0] = *(const float4*)&As[kk][ty * 8];
            *(float4*)&ra[4] = *(const float4*)&As[kk][ty * 8 + 4];
            *(float4*)&rb[0] = *(const float4*)&Bs[kk][tx * 8];
            *(float4*)&rb[4] = *(const float4*)&Bs[kk][tx * 8 + 4];
#pragma unroll
            for (int i = 0; i < 8; i++)
#pragma unroll
                for (int j = 0; j < 8; j++)
                    acc[i][j] += ra[i] * rb[j];
        }
        __syncthreads();
    }
#pragma unroll
    for (int i = 0; i < 8; i++) {
        int row = bx * 128 + ty * 8 + i;
#pragma unroll
        for (int j4 = 0; j4 < 2; j4++) {
            int col = by * 128 + tx * 8 + j4 * 4;
            float4 v;
            v.x = acc[i][j4*4+0];
            v.y = acc[i][j4*4+1];
            v.z = acc[i][j4*4+2];
            v.w = acc[i][j4*4+3];
            if (bias) {
                v.x += bias[col+0]; v.y += bias[col+1];
                v.z += bias[col+2]; v.w += bias[col+3];
            }
            *(float4*)&Cm[(size_t)row * ldc + col] = v;
        }
    }
}

// ---------------- fused attention: per-token, all pooled tables in SMEM ----------------
// grid = 256 (b * 64 chunks of 256 tokens), 256 threads (one token each)
#define ATT_SMEM_FLOATS (HH*KK*DD /*kc*/ + HH*KK*DD /*vc*/ + KK*KK /*cb*/ + 256*65 /*bias rows*/)
__global__ __launch_bounds__(256, 1) void attn_kernel(const float* __restrict__ Ag,
                                                      const float* __restrict__ cb) {
    extern __shared__ float sm[];
    float* kc_s   = sm;                        // 16384
    float* vc_s   = sm + HH*KK*DD;             // 16384
    float* cb_s   = sm + 2*HH*KK*DD;           // 4096
    float* bias_s = sm + 2*HH*KK*DD + KK*KK;   // 256*65 (pad 65 -> conflict-free)

    int tid = threadIdx.x;
    int blk = blockIdx.x;
    int b = blk >> 6;

    // cooperative loads (all float4, coalesced)
    {
        const float4* kc4 = (const float4*)(g_kc + (size_t)b * HH*KK*DD);
        const float4* vc4 = (const float4*)(g_vc + (size_t)b * HH*KK*DD);
        float4* kcs4 = (float4*)kc_s;
        float4* vcs4 = (float4*)vc_s;
        for (int i = tid; i < HH*KK*DD/4; i += 256) { kcs4[i] = kc4[i]; vcs4[i] = vc4[i]; }
        const float4* cb4 = (const float4*)cb;
        float4* cbs4 = (float4*)cb_s;
        for (int i = tid; i < KK*KK/4; i += 256) cbs4[i] = cb4[i];
    }
    __syncthreads();

    size_t n = (size_t)b * NN + (size_t)(blk & 63) * 256 + tid;

    // per-token bias row: bias[l] = sum_k A[n,k] * cb[k,l]
    {
        float biasr[64];
#pragma unroll
        for (int l = 0; l < 64; l++) biasr[l] = 0.0f;
        const float4* arow = (const float4*)(Ag + n * KK);
#pragma unroll
        for (int k4 = 0; k4 < 16; k4++) {
            float4 a4 = arow[k4];
            float avv[4] = {a4.x, a4.y, a4.z, a4.w};
#pragma unroll
            for (int kk = 0; kk < 4; kk++) {
                const float4* cbr = (const float4*)(cb_s + (k4 * 4 + kk) * 64);
#pragma unroll
                for (int l4 = 0; l4 < 16; l4++) {
                    float4 c4 = cbr[l4];                // warp-broadcast
                    biasr[l4*4+0] += avv[kk] * c4.x;
                    biasr[l4*4+1] += avv[kk] * c4.y;
                    biasr[l4*4+2] += avv[kk] * c4.z;
                    biasr[l4*4+3] += avv[kk] * c4.w;
                }
            }
        }
#pragma unroll
        for (int l = 0; l < 64; l++) bias_s[tid * 65 + l] = biasr[l];
    }
    // no sync needed: each thread reads only its own bias row

    const float SCALE = 0.17677669529663689f;  // 32^-0.5

#pragma unroll 1
    for (int h = 0; h < HH; h++) {
        float4 q[8];
        const float4* qg = (const float4*)(g_q + n * CC + h * DD);
#pragma unroll
        for (int i = 0; i < 8; i++) q[i] = qg[i];

        float lg[64];
        const float4* kch = (const float4*)(kc_s + h * KK * DD);
#pragma unroll
        for (int k = 0; k < 64; k++) {
            float s = 0.0f;
#pragma unroll
            for (int i = 0; i < 8; i++) {
                float4 kv = kch[k * 8 + i];             // warp-broadcast LDS.128
                s += q[i].x * kv.x + q[i].y * kv.y + q[i].z * kv.z + q[i].w * kv.w;
            }
            lg[k] = s * SCALE + bias_s[tid * 65 + k];
        }
        float m = lg[0];
#pragma unroll
        for (int k = 1; k < 64; k++) m = fmaxf(m, lg[k]);
        float sum = 0.0f;
#pragma unroll
        for (int k = 0; k < 64; k++) { lg[k] = __expf(lg[k] - m); sum += lg[k]; }
        float inv = 1.0f / sum;

        float4 xo[8];
#pragma unroll
        for (int i = 0; i < 8; i++) xo[i] = make_float4(0.f, 0.f, 0.f, 0.f);
        const float4* vch = (const float4*)(vc_s + h * KK * DD);
#pragma unroll
        for (int k = 0; k < 64; k++) {
            float p = lg[k];
#pragma unroll
            for (int i = 0; i < 8; i++) {
                float4 vv = vch[k * 8 + i];             // warp-broadcast
                xo[i].x += p * vv.x; xo[i].y += p * vv.y;
                xo[i].z += p * vv.z; xo[i].w += p * vv.w;
            }
        }
        float4* xg = (float4*)(g_x + n * CC + h * DD);
#pragma unroll
        for (int i = 0; i < 8; i++) {
            xo[i].x *= inv; xo[i].y *= inv; xo[i].z *= inv; xo[i].w *= inv;
            xg[i] = xo[i];
        }
    }
}

// ---------------- launcher ----------------
extern "C" void kernel_launch(void* const* d_in, const int* in_sizes, int n_in,
                              void* d_out, int out_size) {
    const float* X     = (const float*)d_in[0];   // (B,N,C)
    const float* Ag    = (const float*)d_in[1];   // (B,N,K)
    const float* wqkv  = (const float*)d_in[2];   // (C,3C)
    const float* wproj = (const float*)d_in[3];   // (C,C)
    const float* bproj = (const float*)d_in[4];   // (C,)
    const float* cb    = (const float*)d_in[5];   // (K,K)
    float* out = (float*)d_out;

    float *pq = nullptr, *px = nullptr;
    cudaGetSymbolAddress((void**)&pq, g_q);
    cudaGetSymbolAddress((void**)&px, g_x);

    // 1. zero accumulators
    zero_kernel<<<(BB*KK*CC + 255) / 256, 256>>>();
    // 2. pooled sums S = A^T X, denom
    pool_kernel<<<BB * (NN / 256), 256>>>(X, Ag);
    // 3. pooled K/V clusters
    kcvc_kernel<<<BB * KK, 256>>>(wqkv);
    // 4. Q = X @ Wq  (Wq = first 256 cols of wqkv)
    {
        dim3 grid(BNTOT / 128, CC / 128);
        sgemm_kernel<<<grid, 256>>>(X, wqkv, nullptr, pq,
                                    BNTOT, CC, CC, CC, 3 * CC, CC);
    }
    // 5. fused bias + attention + PV
    {
        size_t shmem = (size_t)ATT_SMEM_FLOATS * sizeof(float);  // 214016 B
        cudaFuncSetAttribute(attn_kernel, cudaFuncAttributeMaxDynamicSharedMemorySize,
                             (int)shmem);
        attn_kernel<<<BB * (NN / 256), 256, shmem>>>(Ag, cb);
    }
    // 6. out = x @ Wproj + b
    {
        dim3 grid(BNTOT / 128, CC / 128);
        sgemm_kernel<<<grid, 256>>>(px, wproj, bproj, out,
                                    BNTOT, CC, CC, CC, CC, CC);
    }
}

// round 3
// speedup vs baseline: 1.3544x; 1.3544x over previous
#include <cuda_runtime.h>
#include <cuda_bf16.h>
#include <cstdint>
#include <math.h>

// Problem constants
#define BB 4
#define NN 16384
#define CC 256
#define HH 8
#define KK 64
#define DD 32
#define BNTOT (BB*NN)   // 65536

// ---------------- scratch (device globals: allocation-free) ----------------
__device__ float g_S[BB*KK*CC];
__device__ float g_denom[BB*KK];
__device__ float g_kc[BB*HH*KK*DD];
__device__ float g_vc[BB*HH*KK*DD];
__device__ float g_q[BNTOT*CC];
__device__ __nv_bfloat16 g_Xhi[BNTOT*CC], g_Xlo[BNTOT*CC];   // split of voxel_features
__device__ __nv_bfloat16 g_xhi[BNTOT*CC], g_xlo[BNTOT*CC];   // split of attn output
__device__ __nv_bfloat16 g_Wqt_hi[CC*CC], g_Wqt_lo[CC*CC];   // Wq^T  [n][k]
__device__ __nv_bfloat16 g_Wpt_hi[CC*CC], g_Wpt_lo[CC*CC];   // Wproj^T [n][k]

// ---------------- small helpers ----------------
__device__ __forceinline__ uint32_t smem_u32(const void* p) {
    uint32_t a;
    asm("{ .reg .u64 t; cvta.to.shared.u64 t, %1; cvt.u32.u64 %0, t; }" : "=r"(a) : "l"(p));
    return a;
}
#define CP16(dst, src) \
    asm volatile("cp.async.cg.shared.global [%0], [%1], 16;" :: "r"(dst), "l"(src))
#define CPCOMMIT() asm volatile("cp.async.commit_group;" ::: "memory")
#define CPWAIT(n)  asm volatile("cp.async.wait_group %0;" :: "n"(n) : "memory")

__device__ __forceinline__ void ldsm_x4(uint32_t* r, uint32_t addr) {
    asm volatile("ldmatrix.sync.aligned.m8n8.x4.shared.b16 {%0,%1,%2,%3}, [%4];"
                 : "=r"(r[0]), "=r"(r[1]), "=r"(r[2]), "=r"(r[3]) : "r"(addr));
}
__device__ __forceinline__ void mma_bf16(float* d, const uint32_t* a,
                                         uint32_t b0, uint32_t b1) {
    asm volatile(
        "mma.sync.aligned.m16n8k16.row.col.f32.bf16.bf16.f32 "
        "{%0,%1,%2,%3}, {%4,%5,%6,%7}, {%8,%9}, {%0,%1,%2,%3};"
        : "+f"(d[0]), "+f"(d[1]), "+f"(d[2]), "+f"(d[3])
        : "r"(a[0]), "r"(a[1]), "r"(a[2]), "r"(a[3]), "r"(b0), "r"(b1));
}

// ---------------- zero scratch accumulators ----------------
__global__ void zero_kernel() {
    int i = blockIdx.x * blockDim.x + threadIdx.x;
    if (i < BB*KK*CC) g_S[i] = 0.0f;
    if (i < BB*KK)    g_denom[i] = 0.0f;
}

// ---------------- split X into bf16 hi/lo ----------------
__global__ __launch_bounds__(256) void convertX_kernel(const float* __restrict__ X) {
    size_t i = ((size_t)blockIdx.x * 256 + threadIdx.x) * 8;
    float4 a = *(const float4*)(X + i);
    float4 b = *(const float4*)(X + i + 4);
    float v[8] = {a.x, a.y, a.z, a.w, b.x, b.y, b.z, b.w};
    __nv_bfloat16 h[8], l[8];
#pragma unroll
    for (int j = 0; j < 8; j++) {
        h[j] = __float2bfloat16(v[j]);
        l[j] = __float2bfloat16(v[j] - __bfloat162float(h[j]));
    }
    *(uint4*)&g_Xhi[i] = *(const uint4*)h;
    *(uint4*)&g_Xlo[i] = *(const uint4*)l;
}

// ---------------- build transposed bf16 hi/lo weights ----------------
__global__ __launch_bounds__(256) void prepW_kernel(const float* __restrict__ wqkv,
                                                    const float* __restrict__ wproj) {
    int n = blockIdx.x, k = threadIdx.x;
    float wq = wqkv[k * (3*CC) + n];      // Wq column n
    float wp = wproj[k * CC + n];
    __nv_bfloat16 qh = __float2bfloat16(wq);
    __nv_bfloat16 ph = __float2bfloat16(wp);
    int o = n * CC + k;
    g_Wqt_hi[o] = qh;
    g_Wqt_lo[o] = __float2bfloat16(wq - __bfloat162float(qh));
    g_Wpt_hi[o] = ph;
    g_Wpt_lo[o] = __float2bfloat16(wp - __bfloat162float(ph));
}

// ---------------- pooling: S[b,k,c] = sum_n A[b,n,k] * X[b,n,c]; denom ----------------
__global__ __launch_bounds__(256) void pool_kernel(const float* __restrict__ X,
                                                   const float* __restrict__ Ag) {
    __shared__ float xs[4][CC];
    __shared__ float as_[4][KK];
    int tid = threadIdx.x;
    int k  = tid & 63;
    int cg = tid >> 6;
    int blk = blockIdx.x;
    int b = blk >> 6;
    size_t rowbase = (size_t)b * NN + (size_t)(blk & 63) * 256;

    float acc[64];
#pragma unroll
    for (int j = 0; j < 64; j++) acc[j] = 0.0f;
    float dsum = 0.0f;

    for (int n0 = 0; n0 < 256; n0 += 4) {
        *(float4*)&xs[cg][k * 4] =
            *(const float4*)(X + (rowbase + n0 + cg) * CC + k * 4);
        as_[cg][k] = Ag[(rowbase + n0 + cg) * KK + k];
        __syncthreads();
#pragma unroll
        for (int u = 0; u < 4; u++) {
            float a = as_[u][k];
            if (cg == 0) dsum += a;
            const float4* xr = (const float4*)&xs[u][cg * 64];
#pragma unroll
            for (int j4 = 0; j4 < 16; j4++) {
                float4 xv = xr[j4];
                acc[j4*4+0] += a * xv.x;
                acc[j4*4+1] += a * xv.y;
                acc[j4*4+2] += a * xv.z;
                acc[j4*4+3] += a * xv.w;
            }
        }
        __syncthreads();
    }
    float* Sout = &g_S[(b * KK + k) * CC + cg * 64];
#pragma unroll
    for (int j = 0; j < 64; j++) atomicAdd(&Sout[j], acc[j]);
    if (cg == 0) atomicAdd(&g_denom[b * KK + k], dsum);
}

// ---------------- kc/vc from S ----------------
__global__ __launch_bounds__(256) void kcvc_kernel(const float* __restrict__ wqkv) {
    int bk = blockIdx.x;
    int b = bk >> 6;
    int k = bk & 63;
    int t = threadIdx.x;
    __shared__ float s_row[CC];
    s_row[t] = g_S[bk * CC + t];
    __syncthreads();
    float inv = 1.0f / (g_denom[bk] + 1e-8f);
    float ak = 0.0f, av = 0.0f;
#pragma unroll 8
    for (int c = 0; c < CC; c++) {
        float s = s_row[c];
        ak += s * wqkv[c * (3*CC) + CC  + t];
        av += s * wqkv[c * (3*CC) + 2*CC + t];
    }
    int h = t >> 5, dd = t & 31;
    int o = ((b * HH + h) * KK + k) * DD + dd;
    g_kc[o] = ak * inv;
    g_vc[o] = av * inv;
}

// ---------------- HMMA bf16 3-split GEMM: C[M,256] = A[M,256] @ W^T (+bias) -------------
// CTA 128x128, 8 warps (warp tile 64x32), extended K = 768 (3 split-products),
// 24 chunks of K=32, 3-stage cp.async pipeline.
#define AST 40                      // padded SMEM row stride (bf16 elems), 80B
#define STAGE_ELE (128 * AST)
#define GEMM_SMEM_BYTES (2 * 3 * STAGE_ELE * 2)   // A + B, 3 stages, bf16

__global__ __launch_bounds__(256, 2) void gemm_bf16x3_mma(
    const __nv_bfloat16* __restrict__ Ahi, const __nv_bfloat16* __restrict__ Alo,
    const __nv_bfloat16* __restrict__ Whi, const __nv_bfloat16* __restrict__ Wlo,
    const float* __restrict__ bias, float* __restrict__ Cout) {
    extern __shared__ __nv_bfloat16 smemb[];
    __nv_bfloat16* As = smemb;                         // [3][128][AST]
    __nv_bfloat16* Bs = smemb + 3 * STAGE_ELE;         // [3][128][AST]
    uint32_t a_sm = smem_u32(As);
    uint32_t b_sm = smem_u32(Bs);

    int tid = threadIdx.x;
    int lane = tid & 31, w = tid >> 5;
    int wr = w >> 2, wc = w & 3;                       // warp grid 2 x 4
    size_t mbase = (size_t)blockIdx.x * 128;
    int nbase = blockIdx.y * 128;

    const __nv_bfloat16* Asp[3] = {Ahi, Ahi, Alo};
    const __nv_bfloat16* Wsp[3] = {Whi, Wlo, Whi};

    int ldrow = tid >> 2;        // 0..63
    int ldwd  = tid & 3;         // 0..3 (16B words within 64B row)

    float acc[4][4][4];
#pragma unroll
    for (int i = 0; i < 4; i++)
#pragma unroll
        for (int j = 0; j < 4; j++)
#pragma unroll
            for (int r = 0; r < 4; r++) acc[i][j][r] = 0.0f;

    auto issue = [&](int c) {
        int s = c >> 3;
        int ko = (c & 7) * 32;
        const __nv_bfloat16* Ap = Asp[s];
        const __nv_bfloat16* Wp = Wsp[s];
        uint32_t sa = a_sm + (uint32_t)((c % 3) * STAGE_ELE) * 2;
        uint32_t sb = b_sm + (uint32_t)((c % 3) * STAGE_ELE) * 2;
#pragma unroll
        for (int t = 0; t < 2; t++) {
            int row = ldrow + t * 64;
            CP16(sa + (uint32_t)(row * AST + ldwd * 8) * 2,
                 Ap + (mbase + row) * CC + ko + ldwd * 8);
            CP16(sb + (uint32_t)(row * AST + ldwd * 8) * 2,
                 Wp + (size_t)(nbase + row) * CC + ko + ldwd * 8);
        }
        CPCOMMIT();
    };

    // ldmatrix lane->coords
    int arow = (lane & 7) + 8 * ((lane >> 3) & 1);
    int akw  = (lane >> 4) * 8;
    int brow = (lane & 7) + 8 * ((lane >> 4) & 1);
    int bkw  = ((lane >> 3) & 1) * 8;

    auto compute = [&](int stage) {
        uint32_t sa = a_sm + (uint32_t)(stage * STAGE_ELE) * 2;
        uint32_t sb = b_sm + (uint32_t)(stage * STAGE_ELE) * 2;
#pragma unroll
        for (int ks = 0; ks < 32; ks += 16) {
            uint32_t afr[4][4];
#pragma unroll
            for (int mt = 0; mt < 4; mt++) {
                uint32_t addr = sa +
                    (uint32_t)(((wr * 64 + mt * 16 + arow) * AST) + ks + akw) * 2;
                ldsm_x4(afr[mt], addr);
            }
            uint32_t bfr[2][4];
#pragma unroll
            for (int nt2 = 0; nt2 < 2; nt2++) {
                uint32_t addr = sb +
                    (uint32_t)(((wc * 32 + nt2 * 16 + brow) * AST) + ks + bkw) * 2;
                ldsm_x4(bfr[nt2], addr);
            }
#pragma unroll
            for (int mt = 0; mt < 4; mt++)
#pragma unroll
                for (int nt = 0; nt < 4; nt++)
                    mma_bf16(acc[mt][nt], afr[mt],
                             bfr[nt >> 1][(nt & 1) * 2],
                             bfr[nt >> 1][(nt & 1) * 2 + 1]);
        }
    };

    issue(0);
    issue(1);
#pragma unroll 1
    for (int c = 0; c < 24; c++) {
        if (c < 22) { CPWAIT(1); } else { CPWAIT(0); }
        __syncthreads();
        if (c + 2 < 24) issue(c + 2);
        compute(c % 3);
    }

    // epilogue
    int g = lane >> 2, ti = lane & 3;
#pragma unroll
    for (int mt = 0; mt < 4; mt++) {
#pragma unroll
        for (int nt = 0; nt < 4; nt++) {
            size_t row = mbase + wr * 64 + mt * 16 + g;
            int col = nbase + wc * 32 + nt * 8 + ti * 2;
            float bx = 0.0f, by = 0.0f;
            if (bias) { bx = bias[col]; by = bias[col + 1]; }
            float2 v0, v1;
            v0.x = acc[mt][nt][0] + bx; v0.y = acc[mt][nt][1] + by;
            v1.x = acc[mt][nt][2] + bx; v1.y = acc[mt][nt][3] + by;
            *(float2*)&Cout[row * CC + col] = v0;
            *(float2*)&Cout[(row + 8) * CC + col] = v1;
        }
    }
}

// ---------------- fused attention; writes bf16 hi/lo splits of x ----------------
#define ATT_SMEM_FLOATS (HH*KK*DD + HH*KK*DD + KK*KK + 256*65)
__global__ __launch_bounds__(256, 1) void attn_kernel(const float* __restrict__ Ag,
                                                      const float* __restrict__ cb) {
    extern __shared__ float sm[];
    float* kc_s   = sm;
    float* vc_s   = sm + HH*KK*DD;
    float* cb_s   = sm + 2*HH*KK*DD;
    float* bias_s = sm + 2*HH*KK*DD + KK*KK;

    int tid = threadIdx.x;
    int blk = blockIdx.x;
    int b = blk >> 6;

    {
        const float4* kc4 = (const float4*)(g_kc + (size_t)b * HH*KK*DD);
        const float4* vc4 = (const float4*)(g_vc + (size_t)b * HH*KK*DD);
        float4* kcs4 = (float4*)kc_s;
        float4* vcs4 = (float4*)vc_s;
        for (int i = tid; i < HH*KK*DD/4; i += 256) { kcs4[i] = kc4[i]; vcs4[i] = vc4[i]; }
        const float4* cb4 = (const float4*)cb;
        float4* cbs4 = (float4*)cb_s;
        for (int i = tid; i < KK*KK/4; i += 256) cbs4[i] = cb4[i];
    }
    __syncthreads();

    size_t n = (size_t)b * NN + (size_t)(blk & 63) * 256 + tid;

    {
        float biasr[64];
#pragma unroll
        for (int l = 0; l < 64; l++) biasr[l] = 0.0f;
        const float4* arow = (const float4*)(Ag + n * KK);
#pragma unroll
        for (int k4 = 0; k4 < 16; k4++) {
            float4 a4 = arow[k4];
            float avv[4] = {a4.x, a4.y, a4.z, a4.w};
#pragma unroll
            for (int kk = 0; kk < 4; kk++) {
                const float4* cbr = (const float4*)(cb_s + (k4 * 4 + kk) * 64);
#pragma unroll
                for (int l4 = 0; l4 < 16; l4++) {
                    float4 c4 = cbr[l4];
                    biasr[l4*4+0] += avv[kk] * c4.x;
                    biasr[l4*4+1] += avv[kk] * c4.y;
                    biasr[l4*4+2] += avv[kk] * c4.z;
                    biasr[l4*4+3] += avv[kk] * c4.w;
                }
            }
        }
#pragma unroll
        for (int l = 0; l < 64; l++) bias_s[tid * 65 + l] = biasr[l];
    }

    const float SCALE = 0.17677669529663689f;

#pragma unroll 1
    for (int h = 0; h < HH; h++) {
        float4 q[8];
        const float4* qg = (const float4*)(g_q + n * CC + h * DD);
#pragma unroll
        for (int i = 0; i < 8; i++) q[i] = qg[i];

        float lg[64];
        const float4* kch = (const float4*)(kc_s + h * KK * DD);
#pragma unroll
        for (int k = 0; k < 64; k++) {
            float s = 0.0f;
#pragma unroll
            for (int i = 0; i < 8; i++) {
                float4 kv = kch[k * 8 + i];
                s += q[i].x * kv.x + q[i].y * kv.y + q[i].z * kv.z + q[i].w * kv.w;
            }
            lg[k] = s * SCALE + bias_s[tid * 65 + k];
        }
        float m = lg[0];
#pragma unroll
        for (int k = 1; k < 64; k++) m = fmaxf(m, lg[k]);
        float sum = 0.0f;
#pragma unroll
        for (int k = 0; k < 64; k++) { lg[k] = __expf(lg[k] - m); sum += lg[k]; }
        float inv = 1.0f / sum;

        float4 xo[8];
#pragma unroll
        for (int i = 0; i < 8; i++) xo[i] = make_float4(0.f, 0.f, 0.f, 0.f);
        const float4* vch = (const float4*)(vc_s + h * KK * DD);
#pragma unroll
        for (int k = 0; k < 64; k++) {
            float p = lg[k];
#pragma unroll
            for (int i = 0; i < 8; i++) {
                float4 vv = vch[k * 8 + i];
                xo[i].x += p * vv.x; xo[i].y += p * vv.y;
                xo[i].z += p * vv.z; xo[i].w += p * vv.w;
            }
        }
        __nv_bfloat16 xh[32], xl[32];
#pragma unroll
        for (int i = 0; i < 8; i++) {
            float vv[4] = {xo[i].x * inv, xo[i].y * inv, xo[i].z * inv, xo[i].w * inv};
#pragma unroll
            for (int cmp = 0; cmp < 4; cmp++) {
                __nv_bfloat16 hh = __float2bfloat16(vv[cmp]);
                xh[i*4+cmp] = hh;
                xl[i*4+cmp] = __float2bfloat16(vv[cmp] - __bfloat162float(hh));
            }
        }
        uint4* dsth = (uint4*)&g_xhi[n * CC + h * DD];
        uint4* dstl = (uint4*)&g_xlo[n * CC + h * DD];
#pragma unroll
        for (int i = 0; i < 4; i++) {
            dsth[i] = ((const uint4*)xh)[i];
            dstl[i] = ((const uint4*)xl)[i];
        }
    }
}

// ---------------- launcher ----------------
extern "C" void kernel_launch(void* const* d_in, const int* in_sizes, int n_in,
                              void* d_out, int out_size) {
    const float* X     = (const float*)d_in[0];
    const float* Ag    = (const float*)d_in[1];
    const float* wqkv  = (const float*)d_in[2];
    const float* wproj = (const float*)d_in[3];
    const float* bproj = (const float*)d_in[4];
    const float* cb    = (const float*)d_in[5];
    float* out = (float*)d_out;

    float *pq = nullptr;
    __nv_bfloat16 *pXhi, *pXlo, *pxhi, *pxlo, *pWqh, *pWql, *pWph, *pWpl;
    cudaGetSymbolAddress((void**)&pq, g_q);
    cudaGetSymbolAddress((void**)&pXhi, g_Xhi);
    cudaGetSymbolAddress((void**)&pXlo, g_Xlo);
    cudaGetSymbolAddress((void**)&pxhi, g_xhi);
    cudaGetSymbolAddress((void**)&pxlo, g_xlo);
    cudaGetSymbolAddress((void**)&pWqh, g_Wqt_hi);
    cudaGetSymbolAddress((void**)&pWql, g_Wqt_lo);
    cudaGetSymbolAddress((void**)&pWph, g_Wpt_hi);
    cudaGetSymbolAddress((void**)&pWpl, g_Wpt_lo);

    cudaFuncSetAttribute(gemm_bf16x3_mma,
                         cudaFuncAttributeMaxDynamicSharedMemorySize, GEMM_SMEM_BYTES);

    // 1. zero accumulators
    zero_kernel<<<(BB*KK*CC + 255) / 256, 256>>>();
    // 2. split inputs for tensor cores
    convertX_kernel<<<(BNTOT*CC) / (256*8), 256>>>(X);
    prepW_kernel<<<CC, 256>>>(wqkv, wproj);
    // 3. pooled sums S = A^T X, denom
    pool_kernel<<<BB * (NN / 256), 256>>>(X, Ag);
    // 4. pooled K/V clusters
    kcvc_kernel<<<BB * KK, 256>>>(wqkv);
    // 5. Q = X @ Wq via HMMA bf16 3-split
    {
        dim3 grid(BNTOT / 128, CC / 128);
        gemm_bf16x3_mma<<<grid, 256, GEMM_SMEM_BYTES>>>(pXhi, pXlo, pWqh, pWql, nullptr, pq);
    }
    // 6. fused bias + attention + PV (writes bf16 split of x)
    {
        size_t shmem = (size_t)ATT_SMEM_FLOATS * sizeof(float);
        cudaFuncSetAttribute(attn_kernel, cudaFuncAttributeMaxDynamicSharedMemorySize,
                             (int)shmem);
        attn_kernel<<<BB * (NN / 256), 256, shmem>>>(Ag, cb);
    }
    // 7. out = x @ Wproj + b via HMMA bf16 3-split
    {
        dim3 grid(BNTOT / 128, CC / 128);
        gemm_bf16x3_mma<<<grid, 256, GEMM_SMEM_BYTES>>>(pxhi, pxlo, pWph, pWpl, bproj, out);
    }
}

// round 4
// speedup vs baseline: 1.3716x; 1.0127x over previous
#include <cuda_runtime.h>
#include <cuda_bf16.h>
#include <cstdint>
#include <math.h>

// Problem constants
#define BB 4
#define NN 16384
#define CC 256
#define HH 8
#define KK 64
#define DD 32
#define BNTOT (BB*NN)   // 65536

// ---------------- scratch (device globals: allocation-free) ----------------
__device__ float g_S[BB*KK*CC];
__device__ float g_denom[BB*KK];
__device__ float g_kc[BB*HH*KK*DD];
__device__ float g_vc[BB*HH*KK*DD];
__device__ float g_q[BNTOT*CC];
__device__ __nv_bfloat16 g_Xhi[BNTOT*CC], g_Xlo[BNTOT*CC];   // split of voxel_features
__device__ __nv_bfloat16 g_xhi[BNTOT*CC], g_xlo[BNTOT*CC];   // split of attn output
__device__ __nv_bfloat16 g_Wqt_hi[CC*CC], g_Wqt_lo[CC*CC];   // Wq^T  [n][k]
__device__ __nv_bfloat16 g_Wpt_hi[CC*CC], g_Wpt_lo[CC*CC];   // Wproj^T [n][k]

// ---------------- small helpers ----------------
__device__ __forceinline__ uint32_t smem_u32(const void* p) {
    uint32_t a;
    asm("{ .reg .u64 t; cvta.to.shared.u64 t, %1; cvt.u32.u64 %0, t; }" : "=r"(a) : "l"(p));
    return a;
}
#define CP16(dst, src) \
    asm volatile("cp.async.cg.shared.global [%0], [%1], 16;" :: "r"(dst), "l"(src))
#define CPCOMMIT() asm volatile("cp.async.commit_group;" ::: "memory")
#define CPWAIT(n)  asm volatile("cp.async.wait_group %0;" :: "n"(n) : "memory")

__device__ __forceinline__ void ldsm_x4(uint32_t* r, uint32_t addr) {
    asm volatile("ldmatrix.sync.aligned.m8n8.x4.shared.b16 {%0,%1,%2,%3}, [%4];"
                 : "=r"(r[0]), "=r"(r[1]), "=r"(r[2]), "=r"(r[3]) : "r"(addr));
}
__device__ __forceinline__ void mma_bf16(float* d, const uint32_t* a,
                                         uint32_t b0, uint32_t b1) {
    asm volatile(
        "mma.sync.aligned.m16n8k16.row.col.f32.bf16.bf16.f32 "
        "{%0,%1,%2,%3}, {%4,%5,%6,%7}, {%8,%9}, {%0,%1,%2,%3};"
        : "+f"(d[0]), "+f"(d[1]), "+f"(d[2]), "+f"(d[3])
        : "r"(a[0]), "r"(a[1]), "r"(a[2]), "r"(a[3]), "r"(b0), "r"(b1));
}

// ---------------- zero scratch accumulators ----------------
__global__ void zero_kernel() {
    int i = blockIdx.x * blockDim.x + threadIdx.x;
    if (i < BB*KK*CC) g_S[i] = 0.0f;
    if (i < BB*KK)    g_denom[i] = 0.0f;
}

// ---------------- split X into bf16 hi/lo ----------------
__global__ __launch_bounds__(256) void convertX_kernel(const float* __restrict__ X) {
    size_t i = ((size_t)blockIdx.x * 256 + threadIdx.x) * 8;
    float4 a = *(const float4*)(X + i);
    float4 b = *(const float4*)(X + i + 4);
    float v[8] = {a.x, a.y, a.z, a.w, b.x, b.y, b.z, b.w};
    __nv_bfloat16 h[8], l[8];
#pragma unroll
    for (int j = 0; j < 8; j++) {
        h[j] = __float2bfloat16(v[j]);
        l[j] = __float2bfloat16(v[j] - __bfloat162float(h[j]));
    }
    *(uint4*)&g_Xhi[i] = *(const uint4*)h;
    *(uint4*)&g_Xlo[i] = *(const uint4*)l;
}

// ---------------- build transposed bf16 hi/lo weights ----------------
__global__ __launch_bounds__(256) void prepW_kernel(const float* __restrict__ wqkv,
                                                    const float* __restrict__ wproj) {
    int n = blockIdx.x, k = threadIdx.x;
    float wq = wqkv[k * (3*CC) + n];      // Wq column n
    float wp = wproj[k * CC + n];
    __nv_bfloat16 qh = __float2bfloat16(wq);
    __nv_bfloat16 ph = __float2bfloat16(wp);
    int o = n * CC + k;
    g_Wqt_hi[o] = qh;
    g_Wqt_lo[o] = __float2bfloat16(wq - __bfloat162float(qh));
    g_Wpt_hi[o] = ph;
    g_Wpt_lo[o] = __float2bfloat16(wp - __bfloat162float(ph));
}

// ---------------- pooling: S[b,k,c] = sum_n A[b,n,k] * X[b,n,c]; denom ----------------
__global__ __launch_bounds__(256) void pool_kernel(const float* __restrict__ X,
                                                   const float* __restrict__ Ag) {
    __shared__ float xs[4][CC];
    __shared__ float as_[4][KK];
    int tid = threadIdx.x;
    int k  = tid & 63;
    int cg = tid >> 6;
    int blk = blockIdx.x;
    int b = blk >> 6;
    size_t rowbase = (size_t)b * NN + (size_t)(blk & 63) * 256;

    float acc[64];
#pragma unroll
    for (int j = 0; j < 64; j++) acc[j] = 0.0f;
    float dsum = 0.0f;

    for (int n0 = 0; n0 < 256; n0 += 4) {
        *(float4*)&xs[cg][k * 4] =
            *(const float4*)(X + (rowbase + n0 + cg) * CC + k * 4);
        as_[cg][k] = Ag[(rowbase + n0 + cg) * KK + k];
        __syncthreads();
#pragma unroll
        for (int u = 0; u < 4; u++) {
            float a = as_[u][k];
            if (cg == 0) dsum += a;
            const float4* xr = (const float4*)&xs[u][cg * 64];
#pragma unroll
            for (int j4 = 0; j4 < 16; j4++) {
                float4 xv = xr[j4];
                acc[j4*4+0] += a * xv.x;
                acc[j4*4+1] += a * xv.y;
                acc[j4*4+2] += a * xv.z;
                acc[j4*4+3] += a * xv.w;
            }
        }
        __syncthreads();
    }
    float* Sout = &g_S[(b * KK + k) * CC + cg * 64];
#pragma unroll
    for (int j = 0; j < 64; j++) atomicAdd(&Sout[j], acc[j]);
    if (cg == 0) atomicAdd(&g_denom[b * KK + k], dsum);
}

// ---------------- kc/vc from S ----------------
__global__ __launch_bounds__(256) void kcvc_kernel(const float* __restrict__ wqkv) {
    int bk = blockIdx.x;
    int b = bk >> 6;
    int k = bk & 63;
    int t = threadIdx.x;
    __shared__ float s_row[CC];
    s_row[t] = g_S[bk * CC + t];
    __syncthreads();
    float inv = 1.0f / (g_denom[bk] + 1e-8f);
    float ak = 0.0f, av = 0.0f;
#pragma unroll 8
    for (int c = 0; c < CC; c++) {
        float s = s_row[c];
        ak += s * wqkv[c * (3*CC) + CC  + t];
        av += s * wqkv[c * (3*CC) + 2*CC + t];
    }
    int h = t >> 5, dd = t & 31;
    int o = ((b * HH + h) * KK + k) * DD + dd;
    g_kc[o] = ak * inv;
    g_vc[o] = av * inv;
}

// ---------------- HMMA bf16 3-split GEMM: C[M,256] = A[M,256] @ W^T (+bias) -------------
// CTA 128x128, 8 warps (warp tile 64x32), extended K = 768 (3 split-products),
// 24 chunks of K=32, 3-stage cp.async pipeline.
#define AST 40                      // padded SMEM row stride (bf16 elems), 80B
#define STAGE_ELE (128 * AST)
#define GEMM_SMEM_BYTES (2 * 3 * STAGE_ELE * 2)   // A + B, 3 stages, bf16

__global__ __launch_bounds__(256, 2) void gemm_bf16x3_mma(
    const __nv_bfloat16* __restrict__ Ahi, const __nv_bfloat16* __restrict__ Alo,
    const __nv_bfloat16* __restrict__ Whi, const __nv_bfloat16* __restrict__ Wlo,
    const float* __restrict__ bias, float* __restrict__ Cout) {
    extern __shared__ __nv_bfloat16 smemb[];
    __nv_bfloat16* As = smemb;                         // [3][128][AST]
    __nv_bfloat16* Bs = smemb + 3 * STAGE_ELE;         // [3][128][AST]
    uint32_t a_sm = smem_u32(As);
    uint32_t b_sm = smem_u32(Bs);

    int tid = threadIdx.x;
    int lane = tid & 31, w = tid >> 5;
    int wr = w >> 2, wc = w & 3;                       // warp grid 2 x 4
    size_t mbase = (size_t)blockIdx.x * 128;
    int nbase = blockIdx.y * 128;

    const __nv_bfloat16* Asp[3] = {Ahi, Ahi, Alo};
    const __nv_bfloat16* Wsp[3] = {Whi, Wlo, Whi};

    int ldrow = tid >> 2;        // 0..63
    int ldwd  = tid & 3;         // 0..3 (16B words within 64B row)

    float acc[4][4][4];
#pragma unroll
    for (int i = 0; i < 4; i++)
#pragma unroll
        for (int j = 0; j < 4; j++)
#pragma unroll
            for (int r = 0; r < 4; r++) acc[i][j][r] = 0.0f;

    auto issue = [&](int c) {
        int s = c >> 3;
        int ko = (c & 7) * 32;
        const __nv_bfloat16* Ap = Asp[s];
        const __nv_bfloat16* Wp = Wsp[s];
        uint32_t sa = a_sm + (uint32_t)((c % 3) * STAGE_ELE) * 2;
        uint32_t sb = b_sm + (uint32_t)((c % 3) * STAGE_ELE) * 2;
#pragma unroll
        for (int t = 0; t < 2; t++) {
            int row = ldrow + t * 64;
            CP16(sa + (uint32_t)(row * AST + ldwd * 8) * 2,
                 Ap + (mbase + row) * CC + ko + ldwd * 8);
            CP16(sb + (uint32_t)(row * AST + ldwd * 8) * 2,
                 Wp + (size_t)(nbase + row) * CC + ko + ldwd * 8);
        }
        CPCOMMIT();
    };

    // ldmatrix lane->coords
    int arow = (lane & 7) + 8 * ((lane >> 3) & 1);
    int akw  = (lane >> 4) * 8;
    int brow = (lane & 7) + 8 * ((lane >> 4) & 1);
    int bkw  = ((lane >> 3) & 1) * 8;

    auto compute = [&](int stage) {
        uint32_t sa = a_sm + (uint32_t)(stage * STAGE_ELE) * 2;
        uint32_t sb = b_sm + (uint32_t)(stage * STAGE_ELE) * 2;
#pragma unroll
        for (int ks = 0; ks < 32; ks += 16) {
            uint32_t afr[4][4];
#pragma unroll
            for (int mt = 0; mt < 4; mt++) {
                uint32_t addr = sa +
                    (uint32_t)(((wr * 64 + mt * 16 + arow) * AST) + ks + akw) * 2;
                ldsm_x4(afr[mt], addr);
            }
            uint32_t bfr[2][4];
#pragma unroll
            for (int nt2 = 0; nt2 < 2; nt2++) {
                uint32_t addr = sb +
                    (uint32_t)(((wc * 32 + nt2 * 16 + brow) * AST) + ks + bkw) * 2;
                ldsm_x4(bfr[nt2], addr);
            }
#pragma unroll
            for (int mt = 0; mt < 4; mt++)
#pragma unroll
                for (int nt = 0; nt < 4; nt++)
                    mma_bf16(acc[mt][nt], afr[mt],
                             bfr[nt >> 1][(nt & 1) * 2],
                             bfr[nt >> 1][(nt & 1) * 2 + 1]);
        }
    };

    issue(0);
    issue(1);
#pragma unroll 1
    for (int c = 0; c < 24; c++) {
        if (c < 22) { CPWAIT(1); } else { CPWAIT(0); }
        __syncthreads();
        if (c + 2 < 24) issue(c + 2);
        compute(c % 3);
    }

    // epilogue
    int g = lane >> 2, ti = lane & 3;
#pragma unroll
    for (int mt = 0; mt < 4; mt++) {
#pragma unroll
        for (int nt = 0; nt < 4; nt++) {
            size_t row = mbase + wr * 64 + mt * 16 + g;
            int col = nbase + wc * 32 + nt * 8 + ti * 2;
            float bx = 0.0f, by = 0.0f;
            if (bias) { bx = bias[col]; by = bias[col + 1]; }
            float2 v0, v1;
            v0.x = acc[mt][nt][0] + bx; v0.y = acc[mt][nt][1] + by;
            v1.x = acc[mt][nt][2] + bx; v1.y = acc[mt][nt][3] + by;
            *(float2*)&Cout[row * CC + col] = v0;
            *(float2*)&Cout[(row + 8) * CC + col] = v1;
        }
    }
}

// ---------------- fused attention; writes bf16 hi/lo splits of x ----------------
#define ATT_SMEM_FLOATS (HH*KK*DD + HH*KK*DD + KK*KK + 256*65)
__global__ __launch_bounds__(256, 1) void attn_kernel(const float* __restrict__ Ag,
                                                      const float* __restrict__ cb) {
    extern __shared__ float sm[];
    float* kc_s   = sm;
    float* vc_s   = sm + HH*KK*DD;
    float* cb_s   = sm + 2*HH*KK*DD;
    float* bias_s = sm + 2*HH*KK*DD + KK*KK;

    int tid = threadIdx.x;
    int blk = blockIdx.x;
    int b = blk >> 6;

    {
        const float4* kc4 = (const float4*)(g_kc + (size_t)b * HH*KK*DD);
        const float4* vc4 = (const float4*)(g_vc + (size_t)b * HH*KK*DD);
        float4* kcs4 = (float4*)kc_s;
        float4* vcs4 = (float4*)vc_s;
        for (int i = tid; i < HH*KK*DD/4; i += 256) { kcs4[i] = kc4[i]; vcs4[i] = vc4[i]; }
        const float4* cb4 = (const float4*)cb;
        float4* cbs4 = (float4*)cb_s;
        for (int i = tid; i < KK*KK/4; i += 256) cbs4[i] = cb4[i];
    }
    __syncthreads();

    size_t n = (size_t)b * NN + (size_t)(blk & 63) * 256 + tid;

    {
        float biasr[64];
#pragma unroll
        for (int l = 0; l < 64; l++) biasr[l] = 0.0f;
        const float4* arow = (const float4*)(Ag + n * KK);
#pragma unroll
        for (int k4 = 0; k4 < 16; k4++) {
            float4 a4 = arow[k4];
            float avv[4] = {a4.x, a4.y, a4.z, a4.w};
#pragma unroll
            for (int kk = 0; kk < 4; kk++) {
                const float4* cbr = (const float4*)(cb_s + (k4 * 4 + kk) * 64);
#pragma unroll
                for (int l4 = 0; l4 < 16; l4++) {
                    float4 c4 = cbr[l4];
                    biasr[l4*4+0] += avv[kk] * c4.x;
                    biasr[l4*4+1] += avv[kk] * c4.y;
                    biasr[l4*4+2] += avv[kk] * c4.z;
                    biasr[l4*4+3] += avv[kk] * c4.w;
                }
            }
        }
#pragma unroll
        for (int l = 0; l < 64; l++) bias_s[tid * 65 + l] = biasr[l];
    }

    const float SCALE = 0.17677669529663689f;

#pragma unroll 1
    for (int h = 0; h < HH; h++) {
        float4 q[8];
        const float4* qg = (const float4*)(g_q + n * CC + h * DD);
#pragma unroll
        for (int i = 0; i < 8; i++) q[i] = qg[i];

        float lg[64];
        const float4* kch = (const float4*)(kc_s + h * KK * DD);
#pragma unroll
        for (int k = 0; k < 64; k++) {
            float s = 0.0f;
#pragma unroll
            for (int i = 0; i < 8; i++) {
                float4 kv = kch[k * 8 + i];
                s += q[i].x * kv.x + q[i].y * kv.y + q[i].z * kv.z + q[i].w * kv.w;
            }
            lg[k] = s * SCALE + bias_s[tid * 65 + k];
        }
        float m = lg[0];
#pragma unroll
        for (int k = 1; k < 64; k++) m = fmaxf(m, lg[k]);
        float sum = 0.0f;
#pragma unroll
        for (int k = 0; k < 64; k++) { lg[k] = __expf(lg[k] - m); sum += lg[k]; }
        float inv = 1.0f / sum;

        float4 xo[8];
#pragma unroll
        for (int i = 0; i < 8; i++) xo[i] = make_float4(0.f, 0.f, 0.f, 0.f);
        const float4* vch = (const float4*)(vc_s + h * KK * DD);
#pragma unroll
        for (int k = 0; k < 64; k++) {
            float p = lg[k];
#pragma unroll
            for (int i = 0; i < 8; i++) {
                float4 vv = vch[k * 8 + i];
                xo[i].x += p * vv.x; xo[i].y += p * vv.y;
                xo[i].z += p * vv.z; xo[i].w += p * vv.w;
            }
        }
        __nv_bfloat16 xh[32], xl[32];
#pragma unroll
        for (int i = 0; i < 8; i++) {
            float vv[4] = {xo[i].x * inv, xo[i].y * inv, xo[i].z * inv, xo[i].w * inv};
#pragma unroll
            for (int cmp = 0; cmp < 4; cmp++) {
                __nv_bfloat16 hh = __float2bfloat16(vv[cmp]);
                xh[i*4+cmp] = hh;
                xl[i*4+cmp] = __float2bfloat16(vv[cmp] - __bfloat162float(hh));
            }
        }
        uint4* dsth = (uint4*)&g_xhi[n * CC + h * DD];
        uint4* dstl = (uint4*)&g_xlo[n * CC + h * DD];
#pragma unroll
        for (int i = 0; i < 4; i++) {
            dsth[i] = ((const uint4*)xh)[i];
            dstl[i] = ((const uint4*)xl)[i];
        }
    }
}

// ---------------- launcher ----------------
extern "C" void kernel_launch(void* const* d_in, const int* in_sizes, int n_in,
                              void* d_out, int out_size) {
    const float* X     = (const float*)d_in[0];
    const float* Ag    = (const float*)d_in[1];
    const float* wqkv  = (const float*)d_in[2];
    const float* wproj = (const float*)d_in[3];
    const float* bproj = (const float*)d_in[4];
    const float* cb    = (const float*)d_in[5];
    float* out = (float*)d_out;

    float *pq = nullptr;
    __nv_bfloat16 *pXhi, *pXlo, *pxhi, *pxlo, *pWqh, *pWql, *pWph, *pWpl;
    cudaGetSymbolAddress((void**)&pq, g_q);
    cudaGetSymbolAddress((void**)&pXhi, g_Xhi);
    cudaGetSymbolAddress((void**)&pXlo, g_Xlo);
    cudaGetSymbolAddress((void**)&pxhi, g_xhi);
    cudaGetSymbolAddress((void**)&pxlo, g_xlo);
    cudaGetSymbolAddress((void**)&pWqh, g_Wqt_hi);
    cudaGetSymbolAddress((void**)&pWql, g_Wqt_lo);
    cudaGetSymbolAddress((void**)&pWph, g_Wpt_hi);
    cudaGetSymbolAddress((void**)&pWpl, g_Wpt_lo);

    cudaFuncSetAttribute(gemm_bf16x3_mma,
                         cudaFuncAttributeMaxDynamicSharedMemorySize, GEMM_SMEM_BYTES);

    // 1. zero accumulators
    zero_kernel<<<(BB*KK*CC + 255) / 256, 256>>>();
    // 2. split inputs for tensor cores
    convertX_kernel<<<(BNTOT*CC) / (256*8), 256>>>(X);
    prepW_kernel<<<CC, 256>>>(wqkv, wproj);
    // 3. pooled sums S = A^T X, denom
    pool_kernel<<<BB * (NN / 256), 256>>>(X, Ag);
    // 4. pooled K/V clusters
    kcvc_kernel<<<BB * KK, 256>>>(wqkv);
    // 5. Q = X @ Wq via HMMA bf16 3-split
    {
        dim3 grid(BNTOT / 128, CC / 128);
        gemm_bf16x3_mma<<<grid, 256, GEMM_SMEM_BYTES>>>(pXhi, pXlo, pWqh, pWql, nullptr, pq);
    }
    // 6. fused bias + attention + PV (writes bf16 split of x)
    {
        size_t shmem = (size_t)ATT_SMEM_FLOATS * sizeof(float);
        cudaFuncSetAttribute(attn_kernel, cudaFuncAttributeMaxDynamicSharedMemorySize,
                             (int)shmem);
        attn_kernel<<<BB * (NN / 256), 256, shmem>>>(Ag, cb);
    }
    // 7. out = x @ Wproj + b via HMMA bf16 3-split
    {
        dim3 grid(BNTOT / 128, CC / 128);
        gemm_bf16x3_mma<<<grid, 256, GEMM_SMEM_BYTES>>>(pxhi, pxlo, pWph, pWpl, bproj, out);
    }
}

// round 5
// speedup vs baseline: 1.6044x; 1.1697x over previous
#include <cuda_runtime.h>
#include <cuda_bf16.h>
#include <cstdint>
#include <math.h>

#define BB 4
#define NN 16384
#define CC 256
#define HH 8
#define KK 64
#define DD 32
#define BNTOT (BB*NN)

// ---------------- scratch ----------------
__device__ float g_S[BB*KK*CC];
__device__ float g_denom[BB*KK];
__device__ float g_kc[BB*HH*KK*DD];
__device__ float g_vc[BB*HH*KK*DD];
__device__ float g_q[BNTOT*CC];
__device__ __nv_bfloat16 g_Xhi[BNTOT*CC], g_Xlo[BNTOT*CC];
__device__ __nv_bfloat16 g_Ahi[BNTOT*KK], g_Alo[BNTOT*KK];
__device__ __nv_bfloat16 g_xhi[BNTOT*CC], g_xlo[BNTOT*CC];
__device__ __nv_bfloat16 g_Wqt_hi[CC*CC], g_Wqt_lo[CC*CC];
__device__ __nv_bfloat16 g_Wpt_hi[CC*CC], g_Wpt_lo[CC*CC];

// ---------------- helpers ----------------
__device__ __forceinline__ uint32_t smem_u32(const void* p) {
    uint32_t a;
    asm("{ .reg .u64 t; cvta.to.shared.u64 t, %1; cvt.u32.u64 %0, t; }" : "=r"(a) : "l"(p));
    return a;
}
#define CP16(dst, src) \
    asm volatile("cp.async.cg.shared.global [%0], [%1], 16;" :: "r"(dst), "l"(src))
#define CPCOMMIT() asm volatile("cp.async.commit_group;" ::: "memory")
#define CPWAIT(n)  asm volatile("cp.async.wait_group %0;" :: "n"(n) : "memory")

__device__ __forceinline__ void ldsm_x4(uint32_t* r, uint32_t addr) {
    asm volatile("ldmatrix.sync.aligned.m8n8.x4.shared.b16 {%0,%1,%2,%3}, [%4];"
                 : "=r"(r[0]), "=r"(r[1]), "=r"(r[2]), "=r"(r[3]) : "r"(addr));
}
__device__ __forceinline__ void ldsm_x4_t(uint32_t* r, uint32_t addr) {
    asm volatile("ldmatrix.sync.aligned.m8n8.x4.trans.shared.b16 {%0,%1,%2,%3}, [%4];"
                 : "=r"(r[0]), "=r"(r[1]), "=r"(r[2]), "=r"(r[3]) : "r"(addr));
}
__device__ __forceinline__ void mma_bf16(float* d, const uint32_t* a,
                                         uint32_t b0, uint32_t b1) {
    asm volatile(
        "mma.sync.aligned.m16n8k16.row.col.f32.bf16.bf16.f32 "
        "{%0,%1,%2,%3}, {%4,%5,%6,%7}, {%8,%9}, {%0,%1,%2,%3};"
        : "+f"(d[0]), "+f"(d[1]), "+f"(d[2]), "+f"(d[3])
        : "r"(a[0]), "r"(a[1]), "r"(a[2]), "r"(a[3]), "r"(b0), "r"(b1));
}

// ---------------- zero accumulators ----------------
__global__ void zero_kernel() {
    int i = blockIdx.x * blockDim.x + threadIdx.x;
    if (i < BB*KK*CC) g_S[i] = 0.0f;
    if (i < BB*KK)    g_denom[i] = 0.0f;
}

// ---------------- splits ----------------
__global__ __launch_bounds__(256) void convertX_kernel(const float* __restrict__ X) {
    size_t i = ((size_t)blockIdx.x * 256 + threadIdx.x) * 8;
    float4 a = *(const float4*)(X + i);
    float4 b = *(const float4*)(X + i + 4);
    float v[8] = {a.x, a.y, a.z, a.w, b.x, b.y, b.z, b.w};
    __nv_bfloat16 h[8], l[8];
#pragma unroll
    for (int j = 0; j < 8; j++) {
        h[j] = __float2bfloat16(v[j]);
        l[j] = __float2bfloat16(v[j] - __bfloat162float(h[j]));
    }
    *(uint4*)&g_Xhi[i] = *(const uint4*)h;
    *(uint4*)&g_Xlo[i] = *(const uint4*)l;
}
__global__ __launch_bounds__(256) void convertA_kernel(const float* __restrict__ Ag) {
    size_t i = ((size_t)blockIdx.x * 256 + threadIdx.x) * 8;
    float4 a = *(const float4*)(Ag + i);
    float4 b = *(const float4*)(Ag + i + 4);
    float v[8] = {a.x, a.y, a.z, a.w, b.x, b.y, b.z, b.w};
    __nv_bfloat16 h[8], l[8];
#pragma unroll
    for (int j = 0; j < 8; j++) {
        h[j] = __float2bfloat16(v[j]);
        l[j] = __float2bfloat16(v[j] - __bfloat162float(h[j]));
    }
    *(uint4*)&g_Ahi[i] = *(const uint4*)h;
    *(uint4*)&g_Alo[i] = *(const uint4*)l;
}

// ---------------- transposed bf16 hi/lo weights ----------------
__global__ __launch_bounds__(256) void prepW_kernel(const float* __restrict__ wqkv,
                                                    const float* __restrict__ wproj) {
    int n = blockIdx.x, k = threadIdx.x;
    float wq = wqkv[k * (3*CC) + n];
    float wp = wproj[k * CC + n];
    __nv_bfloat16 qh = __float2bfloat16(wq);
    __nv_bfloat16 ph = __float2bfloat16(wp);
    int o = n * CC + k;
    g_Wqt_hi[o] = qh;
    g_Wqt_lo[o] = __float2bfloat16(wq - __bfloat162float(qh));
    g_Wpt_hi[o] = ph;
    g_Wpt_lo[o] = __float2bfloat16(wp - __bfloat162float(ph));
}

// ---------------- exact fp32 denom: column sums of A ----------------
__global__ __launch_bounds__(256) void denom_kernel(const float* __restrict__ Ag) {
    __shared__ float red[4][64];
    int blk = blockIdx.x;
    int b = blk >> 4, seg = blk & 15;
    int k = threadIdx.x & 63, rr = threadIdx.x >> 6;
    float s = 0.0f;
    size_t base = (size_t)b * NN + seg * 1024;
#pragma unroll 4
    for (int i = 0; i < 256; i++) s += Ag[(base + rr + i * 4) * KK + k];
    red[rr][k] = s;
    __syncthreads();
    if (threadIdx.x < 64)
        atomicAdd(&g_denom[b * KK + threadIdx.x],
                  red[0][threadIdx.x] + red[1][threadIdx.x] +
                  red[2][threadIdx.x] + red[3][threadIdx.x]);
}

// ---------------- tensor-core pooling: S += A^T X (bf16 3-split, split-K atomics) -------
// grid 128: (b, 32 chunks of 512 tokens). 8 warps, warp tile m32(cluster) x n64(c).
#define PX_ST 264
#define PA_ST 72
#define PX_SIZE (64*PX_ST)
#define PA_SIZE (64*PA_ST)
#define POOL_SMEM ((3*PX_SIZE + 3*PA_SIZE)*2)
__global__ __launch_bounds__(256, 1) void pool_tc_kernel() {
    extern __shared__ __nv_bfloat16 ps[];
    uint32_t sb = smem_u32(ps);
    int tid = threadIdx.x, lane = tid & 31, w = tid >> 5;
    int wm = w >> 2, wn = w & 3;
    int b = blockIdx.x >> 5;
    int nbase = (blockIdx.x & 31) * 512;
    const __nv_bfloat16* Asrc[3] = {g_Ahi, g_Ahi, g_Alo};
    const __nv_bfloat16* Xsrc[3] = {g_Xhi, g_Xlo, g_Xhi};

    float acc[2][8][4];
#pragma unroll
    for (int i = 0; i < 2; i++)
#pragma unroll
        for (int j = 0; j < 8; j++)
#pragma unroll
            for (int r = 0; r < 4; r++) acc[i][j][r] = 0.0f;

    auto issue = [&](int c) {
        int s = c >> 3, kc_ = c & 7, buf = c % 3;
        size_t grow0 = (size_t)b * NN + nbase + kc_ * 64;
#pragma unroll
        for (int i = 0; i < 8; i++) {
            int idx = tid + i * 256;
            int row = idx >> 5, ch = idx & 31;
            CP16(sb + (uint32_t)(buf * PX_SIZE + row * PX_ST + ch * 8) * 2,
                 Xsrc[s] + (grow0 + row) * CC + ch * 8);
        }
#pragma unroll
        for (int i = 0; i < 2; i++) {
            int idx = tid + i * 256;
            int row = idx >> 3, ch = idx & 7;
            CP16(sb + (uint32_t)(3 * PX_SIZE + buf * PA_SIZE + row * PA_ST + ch * 8) * 2,
                 Asrc[s] + (grow0 + row) * KK + ch * 8);
        }
        CPCOMMIT();
    };

    issue(0); issue(1);
#pragma unroll 1
    for (int c = 0; c < 24; c++) {
        if (c < 22) { CPWAIT(1); } else { CPWAIT(0); }
        __syncthreads();
        if (c + 2 < 24) issue(c + 2);
        int buf = c % 3;
        uint32_t xb = sb + (uint32_t)(buf * PX_SIZE) * 2;
        uint32_t ab = sb + (uint32_t)(3 * PX_SIZE + buf * PA_SIZE) * 2;
#pragma unroll
        for (int kt = 0; kt < 4; kt++) {
            uint32_t af[2][4];
#pragma unroll
            for (int mt = 0; mt < 2; mt++) {
                uint32_t r[4];
                ldsm_x4_t(r, ab + (uint32_t)((kt * 16 + (lane & 15)) * PA_ST +
                                             wm * 32 + mt * 16 + (lane >> 4) * 8) * 2);
                af[mt][0] = r[0]; af[mt][1] = r[2]; af[mt][2] = r[1]; af[mt][3] = r[3];
            }
#pragma unroll
            for (int nb = 0; nb < 4; nb++) {
                uint32_t bfr[4];
                ldsm_x4_t(bfr, xb + (uint32_t)((kt * 16 + (lane & 15)) * PX_ST +
                                               wn * 64 + nb * 16 + (lane >> 4) * 8) * 2);
#pragma unroll
                for (int mt = 0; mt < 2; mt++) {
                    mma_bf16(acc[mt][nb*2],   af[mt], bfr[0], bfr[1]);
                    mma_bf16(acc[mt][nb*2+1], af[mt], bfr[2], bfr[3]);
                }
            }
        }
    }
#pragma unroll
    for (int mt = 0; mt < 2; mt++)
#pragma unroll
        for (int nt = 0; nt < 8; nt++) {
            int cl = wm * 32 + mt * 16 + (lane >> 2);
            int col = wn * 64 + nt * 8 + 2 * (lane & 3);
            float* d0 = &g_S[(b * KK + cl) * CC + col];
            atomicAdd(d0,     acc[mt][nt][0]);
            atomicAdd(d0 + 1, acc[mt][nt][1]);
            float* d1 = &g_S[(b * KK + cl + 8) * CC + col];
            atomicAdd(d1,     acc[mt][nt][2]);
            atomicAdd(d1 + 1, acc[mt][nt][3]);
        }
}

// ---------------- kc/vc from S ----------------
__global__ __launch_bounds__(256) void kcvc_kernel(const float* __restrict__ wqkv) {
    int bk = blockIdx.x;
    int b = bk >> 6;
    int k = bk & 63;
    int t = threadIdx.x;
    __shared__ float s_row[CC];
    s_row[t] = g_S[bk * CC + t];
    __syncthreads();
    float inv = 1.0f / (g_denom[bk] + 1e-8f);
    float ak = 0.0f, av = 0.0f;
#pragma unroll 8
    for (int c = 0; c < CC; c++) {
        float s = s_row[c];
        ak += s * wqkv[c * (3*CC) + CC  + t];
        av += s * wqkv[c * (3*CC) + 2*CC + t];
    }
    int h = t >> 5, dd = t & 31;
    int o = ((b * HH + h) * KK + k) * DD + dd;
    g_kc[o] = ak * inv;
    g_vc[o] = av * inv;
}

// ---------------- HMMA bf16 3-split GEMM (unchanged from round 3) ----------------
#define AST 40
#define STAGE_ELE (128 * AST)
#define GEMM_SMEM_BYTES (2 * 3 * STAGE_ELE * 2)
__global__ __launch_bounds__(256, 2) void gemm_bf16x3_mma(
    const __nv_bfloat16* __restrict__ Ahi, const __nv_bfloat16* __restrict__ Alo,
    const __nv_bfloat16* __restrict__ Whi, const __nv_bfloat16* __restrict__ Wlo,
    const float* __restrict__ bias, float* __restrict__ Cout) {
    extern __shared__ __nv_bfloat16 smemb[];
    __nv_bfloat16* As = smemb;
    __nv_bfloat16* Bs = smemb + 3 * STAGE_ELE;
    uint32_t a_sm = smem_u32(As);
    uint32_t b_sm = smem_u32(Bs);

    int tid = threadIdx.x;
    int lane = tid & 31, w = tid >> 5;
    int wr = w >> 2, wc = w & 3;
    size_t mbase = (size_t)blockIdx.x * 128;
    int nbase = blockIdx.y * 128;

    const __nv_bfloat16* Asp[3] = {Ahi, Ahi, Alo};
    const __nv_bfloat16* Wsp[3] = {Whi, Wlo, Whi};

    int ldrow = tid >> 2;
    int ldwd  = tid & 3;

    float acc[4][4][4];
#pragma unroll
    for (int i = 0; i < 4; i++)
#pragma unroll
        for (int j = 0; j < 4; j++)
#pragma unroll
            for (int r = 0; r < 4; r++) acc[i][j][r] = 0.0f;

    auto issue = [&](int c) {
        int s = c >> 3;
        int ko = (c & 7) * 32;
        const __nv_bfloat16* Ap = Asp[s];
        const __nv_bfloat16* Wp = Wsp[s];
        uint32_t sa = a_sm + (uint32_t)((c % 3) * STAGE_ELE) * 2;
        uint32_t sb = b_sm + (uint32_t)((c % 3) * STAGE_ELE) * 2;
#pragma unroll
        for (int t = 0; t < 2; t++) {
            int row = ldrow + t * 64;
            CP16(sa + (uint32_t)(row * AST + ldwd * 8) * 2,
                 Ap + (mbase + row) * CC + ko + ldwd * 8);
            CP16(sb + (uint32_t)(row * AST + ldwd * 8) * 2,
                 Wp + (size_t)(nbase + row) * CC + ko + ldwd * 8);
        }
        CPCOMMIT();
    };

    int arow = (lane & 7) + 8 * ((lane >> 3) & 1);
    int akw  = (lane >> 4) * 8;
    int brow = (lane & 7) + 8 * ((lane >> 4) & 1);
    int bkw  = ((lane >> 3) & 1) * 8;

    auto compute = [&](int stage) {
        uint32_t sa = a_sm + (uint32_t)(stage * STAGE_ELE) * 2;
        uint32_t sb = b_sm + (uint32_t)(stage * STAGE_ELE) * 2;
#pragma unroll
        for (int ks = 0; ks < 32; ks += 16) {
            uint32_t afr[4][4];
#pragma unroll
            for (int mt = 0; mt < 4; mt++)
                ldsm_x4(afr[mt], sa + (uint32_t)(((wr * 64 + mt * 16 + arow) * AST) + ks + akw) * 2);
            uint32_t bfr[2][4];
#pragma unroll
            for (int nt2 = 0; nt2 < 2; nt2++)
                ldsm_x4(bfr[nt2], sb + (uint32_t)(((wc * 32 + nt2 * 16 + brow) * AST) + ks + bkw) * 2);
#pragma unroll
            for (int mt = 0; mt < 4; mt++)
#pragma unroll
                for (int nt = 0; nt < 4; nt++)
                    mma_bf16(acc[mt][nt], afr[mt],
                             bfr[nt >> 1][(nt & 1) * 2],
                             bfr[nt >> 1][(nt & 1) * 2 + 1]);
        }
    };

    issue(0);
    issue(1);
#pragma unroll 1
    for (int c = 0; c < 24; c++) {
        if (c < 22) { CPWAIT(1); } else { CPWAIT(0); }
        __syncthreads();
        if (c + 2 < 24) issue(c + 2);
        compute(c % 3);
    }

    int g = lane >> 2, ti = lane & 3;
#pragma unroll
    for (int mt = 0; mt < 4; mt++) {
#pragma unroll
        for (int nt = 0; nt < 4; nt++) {
            size_t row = mbase + wr * 64 + mt * 16 + g;
            int col = nbase + wc * 32 + nt * 8 + ti * 2;
            float bx = 0.0f, by = 0.0f;
            if (bias) { bx = bias[col]; by = bias[col + 1]; }
            float2 v0, v1;
            v0.x = acc[mt][nt][0] + bx; v0.y = acc[mt][nt][1] + by;
            v1.x = acc[mt][nt][2] + bx; v1.y = acc[mt][nt][3] + by;
            *(float2*)&Cout[row * CC + col] = v0;
            *(float2*)&Cout[(row + 8) * CC + col] = v1;
        }
    }
}

// ---------------- fused attention: per-head double-buffered kc/vc (2 CTAs/SM) ----------
// smem floats: kcv[2][2][2048] @0, cb @8192 (4096), bias @12288 (256*65)
#define ATT_SMEM_FLOATS (8192 + 4096 + 256*65)
__global__ __launch_bounds__(256, 2) void attn_kernel(const float* __restrict__ Ag,
                                                      const float* __restrict__ cb) {
    extern __shared__ float sm[];
    float* cb_s   = sm + 8192;
    float* bias_s = sm + 12288;
    uint32_t sb4 = smem_u32(sm);

    int tid = threadIdx.x;
    int blk = blockIdx.x;
    int b = blk >> 6;

    {
        const float4* cb4 = (const float4*)cb;
        float4* cbs4 = (float4*)cb_s;
        for (int i = tid; i < KK*KK/4; i += 256) cbs4[i] = cb4[i];
    }

    auto issue_head = [&](int h) {
        int st = h & 1;
        size_t src = ((size_t)b * HH + h) * (KK * DD);
#pragma unroll
        for (int j = 0; j < 2; j++) {
            CP16(sb4 + (uint32_t)(st * 4096 + tid * 8 + j * 4) * 4,
                 g_kc + src + tid * 8 + j * 4);
            CP16(sb4 + (uint32_t)(st * 4096 + 2048 + tid * 8 + j * 4) * 4,
                 g_vc + src + tid * 8 + j * 4);
        }
        CPCOMMIT();
    };
    issue_head(0);
    __syncthreads();

    size_t n = (size_t)b * NN + (size_t)(blk & 63) * 256 + tid;

    {   // per-token bias row: bias[l] = sum_k A[n,k] * cb[k,l]
        float biasr[64];
#pragma unroll
        for (int l = 0; l < 64; l++) biasr[l] = 0.0f;
        const float4* arow = (const float4*)(Ag + n * KK);
#pragma unroll
        for (int k4 = 0; k4 < 16; k4++) {
            float4 a4 = arow[k4];
            float avv[4] = {a4.x, a4.y, a4.z, a4.w};
#pragma unroll
            for (int kk = 0; kk < 4; kk++) {
                const float4* cbr = (const float4*)(cb_s + (k4 * 4 + kk) * 64);
#pragma unroll
                for (int l4 = 0; l4 < 16; l4++) {
                    float4 c4 = cbr[l4];
                    biasr[l4*4+0] += avv[kk] * c4.x;
                    biasr[l4*4+1] += avv[kk] * c4.y;
                    biasr[l4*4+2] += avv[kk] * c4.z;
                    biasr[l4*4+3] += avv[kk] * c4.w;
                }
            }
        }
#pragma unroll
        for (int l = 0; l < 64; l++) bias_s[tid * 65 + l] = biasr[l];
    }

    const float SCALE = 0.17677669529663689f;

#pragma unroll 1
    for (int h = 0; h < HH; h++) {
        CPWAIT(0);
        __syncthreads();
        if (h + 1 < HH) issue_head(h + 1);
        int st = h & 1;
        const float* kch_f = sm + st * 4096;
        const float* vch_f = sm + st * 4096 + 2048;

        float4 q[8];
        const float4* qg = (const float4*)(g_q + n * CC + h * DD);
#pragma unroll
        for (int i = 0; i < 8; i++) q[i] = qg[i];

        float lg[64];
        const float4* kch = (const float4*)kch_f;
#pragma unroll
        for (int k = 0; k < 64; k++) {
            float s = 0.0f;
#pragma unroll
            for (int i = 0; i < 8; i++) {
                float4 kv = kch[k * 8 + i];
                s += q[i].x * kv.x + q[i].y * kv.y + q[i].z * kv.z + q[i].w * kv.w;
            }
            lg[k] = s * SCALE + bias_s[tid * 65 + k];
        }
        float m = lg[0];
#pragma unroll
        for (int k = 1; k < 64; k++) m = fmaxf(m, lg[k]);
        float sum = 0.0f;
#pragma unroll
        for (int k = 0; k < 64; k++) { lg[k] = __expf(lg[k] - m); sum += lg[k]; }
        float inv = 1.0f / sum;

        float4 xo[8];
#pragma unroll
        for (int i = 0; i < 8; i++) xo[i] = make_float4(0.f, 0.f, 0.f, 0.f);
        const float4* vch = (const float4*)vch_f;
#pragma unroll
        for (int k = 0; k < 64; k++) {
            float p = lg[k];
#pragma unroll
            for (int i = 0; i < 8; i++) {
                float4 vv = vch[k * 8 + i];
                xo[i].x += p * vv.x; xo[i].y += p * vv.y;
                xo[i].z += p * vv.z; xo[i].w += p * vv.w;
            }
        }
        __nv_bfloat16 xh[32], xl[32];
#pragma unroll
        for (int i = 0; i < 8; i++) {
            float vv[4] = {xo[i].x * inv, xo[i].y * inv, xo[i].z * inv, xo[i].w * inv};
#pragma unroll
            for (int cmp = 0; cmp < 4; cmp++) {
                __nv_bfloat16 hh = __float2bfloat16(vv[cmp]);
                xh[i*4+cmp] = hh;
                xl[i*4+cmp] = __float2bfloat16(vv[cmp] - __bfloat162float(hh));
            }
        }
        uint4* dsth = (uint4*)&g_xhi[n * CC + h * DD];
        uint4* dstl = (uint4*)&g_xlo[n * CC + h * DD];
#pragma unroll
        for (int i = 0; i < 4; i++) {
            dsth[i] = ((const uint4*)xh)[i];
            dstl[i] = ((const uint4*)xl)[i];
        }
    }
}

// ---------------- launcher ----------------
extern "C" void kernel_launch(void* const* d_in, const int* in_sizes, int n_in,
                              void* d_out, int out_size) {
    const float* X     = (const float*)d_in[0];
    const float* Ag    = (const float*)d_in[1];
    const float* wqkv  = (const float*)d_in[2];
    const float* wproj = (const float*)d_in[3];
    const float* bproj = (const float*)d_in[4];
    const float* cb    = (const float*)d_in[5];
    float* out = (float*)d_out;

    float *pq = nullptr;
    __nv_bfloat16 *pXhi, *pXlo, *pxhi, *pxlo, *pWqh, *pWql, *pWph, *pWpl;
    cudaGetSymbolAddress((void**)&pq, g_q);
    cudaGetSymbolAddress((void**)&pXhi, g_Xhi);
    cudaGetSymbolAddress((void**)&pXlo, g_Xlo);
    cudaGetSymbolAddress((void**)&pxhi, g_xhi);
    cudaGetSymbolAddress((void**)&pxlo, g_xlo);
    cudaGetSymbolAddress((void**)&pWqh, g_Wqt_hi);
    cudaGetSymbolAddress((void**)&pWql, g_Wqt_lo);
    cudaGetSymbolAddress((void**)&pWph, g_Wpt_hi);
    cudaGetSymbolAddress((void**)&pWpl, g_Wpt_lo);

    cudaFuncSetAttribute(gemm_bf16x3_mma,
                         cudaFuncAttributeMaxDynamicSharedMemorySize, GEMM_SMEM_BYTES);
    cudaFuncSetAttribute(pool_tc_kernel,
                         cudaFuncAttributeMaxDynamicSharedMemorySize, POOL_SMEM);
    cudaFuncSetAttribute(attn_kernel,
                         cudaFuncAttributeMaxDynamicSharedMemorySize,
                         ATT_SMEM_FLOATS * (int)sizeof(float));

    zero_kernel<<<(BB*KK*CC + 255) / 256, 256>>>();
    convertX_kernel<<<(BNTOT*CC) / (256*8), 256>>>(X);
    convertA_kernel<<<(BNTOT*KK) / (256*8), 256>>>(Ag);
    prepW_kernel<<<CC, 256>>>(wqkv, wproj);
    denom_kernel<<<BB * 16, 256>>>(Ag);
    pool_tc_kernel<<<BB * 32, 256, POOL_SMEM>>>();
    kcvc_kernel<<<BB * KK, 256>>>(wqkv);
    {
        dim3 grid(BNTOT / 128, CC / 128);
        gemm_bf16x3_mma<<<grid, 256, GEMM_SMEM_BYTES>>>(pXhi, pXlo, pWqh, pWql, nullptr, pq);
    }
    attn_kernel<<<BB * (NN / 256), 256, ATT_SMEM_FLOATS * sizeof(float)>>>(Ag, cb);
    {
        dim3 grid(BNTOT / 128, CC / 128);
        gemm_bf16x3_mma<<<grid, 256, GEMM_SMEM_BYTES>>>(pxhi, pxlo, pWph, pWpl, bproj, out);
    }
}

// round 6
// speedup vs baseline: 1.6124x; 1.0050x over previous
#include <cuda_runtime.h>
#include <cuda_bf16.h>
#include <cstdint>
#include <math.h>

#define BB 4
#define NN 16384
#define CC 256
#define HH 8
#define KK 64
#define DD 32
#define BNTOT (BB*NN)

// ---------------- scratch ----------------
__device__ float g_S[BB*KK*CC];
__device__ float g_denom[BB*KK];
__device__ float g_kc[BB*HH*KK*DD];
__device__ float g_vc[BB*HH*KK*DD];
__device__ float g_q[BNTOT*CC];
__device__ float g_bias[BNTOT*KK];
__device__ __nv_bfloat16 g_Xhi[BNTOT*CC], g_Xlo[BNTOT*CC];
__device__ __nv_bfloat16 g_Ahi[BNTOT*KK], g_Alo[BNTOT*KK];
__device__ __nv_bfloat16 g_xhi[BNTOT*CC], g_xlo[BNTOT*CC];
__device__ __nv_bfloat16 g_Wqt_hi[CC*CC], g_Wqt_lo[CC*CC];
__device__ __nv_bfloat16 g_Wpt_hi[CC*CC], g_Wpt_lo[CC*CC];

// ---------------- helpers ----------------
__device__ __forceinline__ uint32_t smem_u32(const void* p) {
    uint32_t a;
    asm("{ .reg .u64 t; cvta.to.shared.u64 t, %1; cvt.u32.u64 %0, t; }" : "=r"(a) : "l"(p));
    return a;
}
#define CP16(dst, src) \
    asm volatile("cp.async.cg.shared.global [%0], [%1], 16;" :: "r"(dst), "l"(src))
#define CPCOMMIT() asm volatile("cp.async.commit_group;" ::: "memory")
#define CPWAIT(n)  asm volatile("cp.async.wait_group %0;" :: "n"(n) : "memory")

__device__ __forceinline__ void ldsm_x4(uint32_t* r, uint32_t addr) {
    asm volatile("ldmatrix.sync.aligned.m8n8.x4.shared.b16 {%0,%1,%2,%3}, [%4];"
                 : "=r"(r[0]), "=r"(r[1]), "=r"(r[2]), "=r"(r[3]) : "r"(addr));
}
__device__ __forceinline__ void ldsm_x4_t(uint32_t* r, uint32_t addr) {
    asm volatile("ldmatrix.sync.aligned.m8n8.x4.trans.shared.b16 {%0,%1,%2,%3}, [%4];"
                 : "=r"(r[0]), "=r"(r[1]), "=r"(r[2]), "=r"(r[3]) : "r"(addr));
}
__device__ __forceinline__ void mma_bf16(float* d, const uint32_t* a,
                                         uint32_t b0, uint32_t b1) {
    asm volatile(
        "mma.sync.aligned.m16n8k16.row.col.f32.bf16.bf16.f32 "
        "{%0,%1,%2,%3}, {%4,%5,%6,%7}, {%8,%9}, {%0,%1,%2,%3};"
        : "+f"(d[0]), "+f"(d[1]), "+f"(d[2]), "+f"(d[3])
        : "r"(a[0]), "r"(a[1]), "r"(a[2]), "r"(a[3]), "r"(b0), "r"(b1));
}

// ---------------- zero accumulators ----------------
__global__ void zero_kernel() {
    int i = blockIdx.x * blockDim.x + threadIdx.x;
    if (i < BB*KK*CC) g_S[i] = 0.0f;
    if (i < BB*KK)    g_denom[i] = 0.0f;
}

// ---------------- splits ----------------
__global__ __launch_bounds__(256) void convertX_kernel(const float* __restrict__ X) {
    size_t i = ((size_t)blockIdx.x * 256 + threadIdx.x) * 8;
    float4 a = *(const float4*)(X + i);
    float4 b = *(const float4*)(X + i + 4);
    float v[8] = {a.x, a.y, a.z, a.w, b.x, b.y, b.z, b.w};
    __nv_bfloat16 h[8], l[8];
#pragma unroll
    for (int j = 0; j < 8; j++) {
        h[j] = __float2bfloat16(v[j]);
        l[j] = __float2bfloat16(v[j] - __bfloat162float(h[j]));
    }
    *(uint4*)&g_Xhi[i] = *(const uint4*)h;
    *(uint4*)&g_Xlo[i] = *(const uint4*)l;
}
__global__ __launch_bounds__(256) void convertA_kernel(const float* __restrict__ Ag) {
    size_t i = ((size_t)blockIdx.x * 256 + threadIdx.x) * 8;
    float4 a = *(const float4*)(Ag + i);
    float4 b = *(const float4*)(Ag + i + 4);
    float v[8] = {a.x, a.y, a.z, a.w, b.x, b.y, b.z, b.w};
    __nv_bfloat16 h[8], l[8];
#pragma unroll
    for (int j = 0; j < 8; j++) {
        h[j] = __float2bfloat16(v[j]);
        l[j] = __float2bfloat16(v[j] - __bfloat162float(h[j]));
    }
    *(uint4*)&g_Ahi[i] = *(const uint4*)h;
    *(uint4*)&g_Alo[i] = *(const uint4*)l;
}

// ---------------- transposed bf16 hi/lo weights ----------------
__global__ __launch_bounds__(256) void prepW_kernel(const float* __restrict__ wqkv,
                                                    const float* __restrict__ wproj) {
    int n = blockIdx.x, k = threadIdx.x;
    float wq = wqkv[k * (3*CC) + n];
    float wp = wproj[k * CC + n];
    __nv_bfloat16 qh = __float2bfloat16(wq);
    __nv_bfloat16 ph = __float2bfloat16(wp);
    int o = n * CC + k;
    g_Wqt_hi[o] = qh;
    g_Wqt_lo[o] = __float2bfloat16(wq - __bfloat162float(qh));
    g_Wpt_hi[o] = ph;
    g_Wpt_lo[o] = __float2bfloat16(wp - __bfloat162float(ph));
}

// ---------------- exact fp32 denom: column sums of A ----------------
__global__ __launch_bounds__(256) void denom_kernel(const float* __restrict__ Ag) {
    __shared__ float red[4][64];
    int blk = blockIdx.x;
    int b = blk >> 4, seg = blk & 15;
    int k = threadIdx.x & 63, rr = threadIdx.x >> 6;
    float s = 0.0f;
    size_t base = (size_t)b * NN + seg * 1024;
#pragma unroll 4
    for (int i = 0; i < 256; i++) s += Ag[(base + rr + i * 4) * KK + k];
    red[rr][k] = s;
    __syncthreads();
    if (threadIdx.x < 64)
        atomicAdd(&g_denom[b * KK + threadIdx.x],
                  red[0][threadIdx.x] + red[1][threadIdx.x] +
                  red[2][threadIdx.x] + red[3][threadIdx.x]);
}

// ---------------- bias = A @ cluster_bias (fp32, standalone) ----------------
__global__ __launch_bounds__(256) void bias_kernel(const float* __restrict__ Ag,
                                                   const float* __restrict__ cb) {
    __shared__ float cb_s[KK*KK];
    int tid = threadIdx.x;
    {
        const float4* cb4 = (const float4*)cb;
        float4* cbs4 = (float4*)cb_s;
        for (int i = tid; i < KK*KK/4; i += 256) cbs4[i] = cb4[i];
    }
    __syncthreads();
    size_t n = (size_t)blockIdx.x * 256 + tid;
    float biasr[64];
#pragma unroll
    for (int l = 0; l < 64; l++) biasr[l] = 0.0f;
    const float4* arow = (const float4*)(Ag + n * KK);
#pragma unroll
    for (int k4 = 0; k4 < 16; k4++) {
        float4 a4 = arow[k4];
        float avv[4] = {a4.x, a4.y, a4.z, a4.w};
#pragma unroll
        for (int kk = 0; kk < 4; kk++) {
            const float4* cbr = (const float4*)(cb_s + (k4 * 4 + kk) * 64);
#pragma unroll
            for (int l4 = 0; l4 < 16; l4++) {
                float4 c4 = cbr[l4];
                biasr[l4*4+0] += avv[kk] * c4.x;
                biasr[l4*4+1] += avv[kk] * c4.y;
                biasr[l4*4+2] += avv[kk] * c4.z;
                biasr[l4*4+3] += avv[kk] * c4.w;
            }
        }
    }
    float4* dst = (float4*)(g_bias + n * KK);
#pragma unroll
    for (int l4 = 0; l4 < 16; l4++)
        dst[l4] = make_float4(biasr[l4*4], biasr[l4*4+1], biasr[l4*4+2], biasr[l4*4+3]);
}

// ---------------- tensor-core pooling: S += A^T X (bf16 3-split, split-K atomics) -------
#define PX_ST 264
#define PA_ST 72
#define PX_SIZE (64*PX_ST)
#define PA_SIZE (64*PA_ST)
#define POOL_SMEM ((3*PX_SIZE + 3*PA_SIZE)*2)
__global__ __launch_bounds__(256, 1) void pool_tc_kernel() {
    extern __shared__ __nv_bfloat16 ps[];
    uint32_t sb = smem_u32(ps);
    int tid = threadIdx.x, lane = tid & 31, w = tid >> 5;
    int wm = w >> 2, wn = w & 3;
    int b = blockIdx.x >> 5;
    int nbase = (blockIdx.x & 31) * 512;
    const __nv_bfloat16* Asrc[3] = {g_Ahi, g_Ahi, g_Alo};
    const __nv_bfloat16* Xsrc[3] = {g_Xhi, g_Xlo, g_Xhi};

    float acc[2][8][4];
#pragma unroll
    for (int i = 0; i < 2; i++)
#pragma unroll
        for (int j = 0; j < 8; j++)
#pragma unroll
            for (int r = 0; r < 4; r++) acc[i][j][r] = 0.0f;

    auto issue = [&](int c) {
        int s = c >> 3, kc_ = c & 7, buf = c % 3;
        size_t grow0 = (size_t)b * NN + nbase + kc_ * 64;
#pragma unroll
        for (int i = 0; i < 8; i++) {
            int idx = tid + i * 256;
            int row = idx >> 5, ch = idx & 31;
            CP16(sb + (uint32_t)(buf * PX_SIZE + row * PX_ST + ch * 8) * 2,
                 Xsrc[s] + (grow0 + row) * CC + ch * 8);
        }
#pragma unroll
        for (int i = 0; i < 2; i++) {
            int idx = tid + i * 256;
            int row = idx >> 3, ch = idx & 7;
            CP16(sb + (uint32_t)(3 * PX_SIZE + buf * PA_SIZE + row * PA_ST + ch * 8) * 2,
                 Asrc[s] + (grow0 + row) * KK + ch * 8);
        }
        CPCOMMIT();
    };

    issue(0); issue(1);
#pragma unroll 1
    for (int c = 0; c < 24; c++) {
        if (c < 22) { CPWAIT(1); } else { CPWAIT(0); }
        __syncthreads();
        if (c + 2 < 24) issue(c + 2);
        int buf = c % 3;
        uint32_t xb = sb + (uint32_t)(buf * PX_SIZE) * 2;
        uint32_t ab = sb + (uint32_t)(3 * PX_SIZE + buf * PA_SIZE) * 2;
#pragma unroll
        for (int kt = 0; kt < 4; kt++) {
            uint32_t af[2][4];
#pragma unroll
            for (int mt = 0; mt < 2; mt++) {
                uint32_t r[4];
                ldsm_x4_t(r, ab + (uint32_t)((kt * 16 + (lane & 15)) * PA_ST +
                                             wm * 32 + mt * 16 + (lane >> 4) * 8) * 2);
                af[mt][0] = r[0]; af[mt][1] = r[2]; af[mt][2] = r[1]; af[mt][3] = r[3];
            }
#pragma unroll
            for (int nb = 0; nb < 4; nb++) {
                uint32_t bfr[4];
                ldsm_x4_t(bfr, xb + (uint32_t)((kt * 16 + (lane & 15)) * PX_ST +
                                               wn * 64 + nb * 16 + (lane >> 4) * 8) * 2);
#pragma unroll
                for (int mt = 0; mt < 2; mt++) {
                    mma_bf16(acc[mt][nb*2],   af[mt], bfr[0], bfr[1]);
                    mma_bf16(acc[mt][nb*2+1], af[mt], bfr[2], bfr[3]);
                }
            }
        }
    }
#pragma unroll
    for (int mt = 0; mt < 2; mt++)
#pragma unroll
        for (int nt = 0; nt < 8; nt++) {
            int cl = wm * 32 + mt * 16 + (lane >> 2);
            int col = wn * 64 + nt * 8 + 2 * (lane & 3);
            float* d0 = &g_S[(b * KK + cl) * CC + col];
            atomicAdd(d0,     acc[mt][nt][0]);
            atomicAdd(d0 + 1, acc[mt][nt][1]);
            float* d1 = &g_S[(b * KK + cl + 8) * CC + col];
            atomicAdd(d1,     acc[mt][nt][2]);
            atomicAdd(d1 + 1, acc[mt][nt][3]);
        }
}

// ---------------- kc/vc from S ----------------
__global__ __launch_bounds__(256) void kcvc_kernel(const float* __restrict__ wqkv) {
    int bk = blockIdx.x;
    int b = bk >> 6;
    int k = bk & 63;
    int t = threadIdx.x;
    __shared__ float s_row[CC];
    s_row[t] = g_S[bk * CC + t];
    __syncthreads();
    float inv = 1.0f / (g_denom[bk] + 1e-8f);
    float ak = 0.0f, av = 0.0f;
#pragma unroll 8
    for (int c = 0; c < CC; c++) {
        float s = s_row[c];
        ak += s * wqkv[c * (3*CC) + CC  + t];
        av += s * wqkv[c * (3*CC) + 2*CC + t];
    }
    int h = t >> 5, dd = t & 31;
    int o = ((b * HH + h) * KK + k) * DD + dd;
    g_kc[o] = ak * inv;
    g_vc[o] = av * inv;
}

// ---------------- HMMA bf16 3-split GEMM ----------------
#define AST 40
#define STAGE_ELE (128 * AST)
#define GEMM_SMEM_BYTES (2 * 3 * STAGE_ELE * 2)
__global__ __launch_bounds__(256, 2) void gemm_bf16x3_mma(
    const __nv_bfloat16* __restrict__ Ahi, const __nv_bfloat16* __restrict__ Alo,
    const __nv_bfloat16* __restrict__ Whi, const __nv_bfloat16* __restrict__ Wlo,
    const float* __restrict__ bias, float* __restrict__ Cout) {
    extern __shared__ __nv_bfloat16 smemb[];
    __nv_bfloat16* As = smemb;
    __nv_bfloat16* Bs = smemb + 3 * STAGE_ELE;
    uint32_t a_sm = smem_u32(As);
    uint32_t b_sm = smem_u32(Bs);

    int tid = threadIdx.x;
    int lane = tid & 31, w = tid >> 5;
    int wr = w >> 2, wc = w & 3;
    size_t mbase = (size_t)blockIdx.x * 128;
    int nbase = blockIdx.y * 128;

    const __nv_bfloat16* Asp[3] = {Ahi, Ahi, Alo};
    const __nv_bfloat16* Wsp[3] = {Whi, Wlo, Whi};

    int ldrow = tid >> 2;
    int ldwd  = tid & 3;

    float acc[4][4][4];
#pragma unroll
    for (int i = 0; i < 4; i++)
#pragma unroll
        for (int j = 0; j < 4; j++)
#pragma unroll
            for (int r = 0; r < 4; r++) acc[i][j][r] = 0.0f;

    auto issue = [&](int c) {
        int s = c >> 3;
        int ko = (c & 7) * 32;
        const __nv_bfloat16* Ap = Asp[s];
        const __nv_bfloat16* Wp = Wsp[s];
        uint32_t sa = a_sm + (uint32_t)((c % 3) * STAGE_ELE) * 2;
        uint32_t sb = b_sm + (uint32_t)((c % 3) * STAGE_ELE) * 2;
#pragma unroll
        for (int t = 0; t < 2; t++) {
            int row = ldrow + t * 64;
            CP16(sa + (uint32_t)(row * AST + ldwd * 8) * 2,
                 Ap + (mbase + row) * CC + ko + ldwd * 8);
            CP16(sb + (uint32_t)(row * AST + ldwd * 8) * 2,
                 Wp + (size_t)(nbase + row) * CC + ko + ldwd * 8);
        }
        CPCOMMIT();
    };

    int arow = (lane & 7) + 8 * ((lane >> 3) & 1);
    int akw  = (lane >> 4) * 8;
    int brow = (lane & 7) + 8 * ((lane >> 4) & 1);
    int bkw  = ((lane >> 3) & 1) * 8;

    auto compute = [&](int stage) {
        uint32_t sa = a_sm + (uint32_t)(stage * STAGE_ELE) * 2;
        uint32_t sb = b_sm + (uint32_t)(stage * STAGE_ELE) * 2;
#pragma unroll
        for (int ks = 0; ks < 32; ks += 16) {
            uint32_t afr[4][4];
#pragma unroll
            for (int mt = 0; mt < 4; mt++)
                ldsm_x4(afr[mt], sa + (uint32_t)(((wr * 64 + mt * 16 + arow) * AST) + ks + akw) * 2);
            uint32_t bfr[2][4];
#pragma unroll
            for (int nt2 = 0; nt2 < 2; nt2++)
                ldsm_x4(bfr[nt2], sb + (uint32_t)(((wc * 32 + nt2 * 16 + brow) * AST) + ks + bkw) * 2);
#pragma unroll
            for (int mt = 0; mt < 4; mt++)
#pragma unroll
                for (int nt = 0; nt < 4; nt++)
                    mma_bf16(acc[mt][nt], afr[mt],
                             bfr[nt >> 1][(nt & 1) * 2],
                             bfr[nt >> 1][(nt & 1) * 2 + 1]);
        }
    };

    issue(0);
    issue(1);
#pragma unroll 1
    for (int c = 0; c < 24; c++) {
        if (c < 22) { CPWAIT(1); } else { CPWAIT(0); }
        __syncthreads();
        if (c + 2 < 24) issue(c + 2);
        compute(c % 3);
    }

    int g = lane >> 2, ti = lane & 3;
#pragma unroll
    for (int mt = 0; mt < 4; mt++) {
#pragma unroll
        for (int nt = 0; nt < 4; nt++) {
            size_t row = mbase + wr * 64 + mt * 16 + g;
            int col = nbase + wc * 32 + nt * 8 + ti * 2;
            float bx = 0.0f, by = 0.0f;
            if (bias) { bx = bias[col]; by = bias[col + 1]; }
            float2 v0, v1;
            v0.x = acc[mt][nt][0] + bx; v0.y = acc[mt][nt][1] + by;
            v1.x = acc[mt][nt][2] + bx; v1.y = acc[mt][nt][3] + by;
            *(float2*)&Cout[row * CC + col] = v0;
            *(float2*)&Cout[(row + 8) * CC + col] = v1;
        }
    }
}

// ---------------- slim attention: 32KB smem, bias from global, 2 CTAs/SM ----------------
#define ATT_SMEM_FLOATS (2 * 4096)
__global__ __launch_bounds__(256, 2) void attn_kernel() {
    extern __shared__ float sm[];
    uint32_t sb4 = smem_u32(sm);

    int tid = threadIdx.x;
    int blk = blockIdx.x;
    int b = blk >> 6;

    auto issue_head = [&](int h) {
        int st = h & 1;
        size_t src = ((size_t)b * HH + h) * (KK * DD);
#pragma unroll
        for (int j = 0; j < 2; j++) {
            CP16(sb4 + (uint32_t)(st * 4096 + tid * 8 + j * 4) * 4,
                 g_kc + src + tid * 8 + j * 4);
            CP16(sb4 + (uint32_t)(st * 4096 + 2048 + tid * 8 + j * 4) * 4,
                 g_vc + src + tid * 8 + j * 4);
        }
        CPCOMMIT();
    };
    issue_head(0);

    size_t n = (size_t)b * NN + (size_t)(blk & 63) * 256 + tid;
    const float SCALE = 0.17677669529663689f;
    const float4* biasg = (const float4*)(g_bias + n * KK);

#pragma unroll 1
    for (int h = 0; h < HH; h++) {
        CPWAIT(0);
        __syncthreads();
        if (h + 1 < HH) issue_head(h + 1);
        int st = h & 1;
        const float4* kch = (const float4*)(sm + st * 4096);
        const float4* vch = (const float4*)(sm + st * 4096 + 2048);

        float4 q[8];
        const float4* qg = (const float4*)(g_q + n * CC + h * DD);
#pragma unroll
        for (int i = 0; i < 8; i++) q[i] = qg[i];

        // init logits with bias (L2-resident re-read per head)
        float lg[64];
#pragma unroll
        for (int k4 = 0; k4 < 16; k4++) {
            float4 bv = biasg[k4];
            lg[k4*4+0] = bv.x; lg[k4*4+1] = bv.y;
            lg[k4*4+2] = bv.z; lg[k4*4+3] = bv.w;
        }
#pragma unroll
        for (int k = 0; k < 64; k++) {
            float s = 0.0f;
#pragma unroll
            for (int i = 0; i < 8; i++) {
                float4 kv = kch[k * 8 + i];
                s += q[i].x * kv.x + q[i].y * kv.y + q[i].z * kv.z + q[i].w * kv.w;
            }
            lg[k] = fmaf(s, SCALE, lg[k]);
        }
        float m = lg[0];
#pragma unroll
        for (int k = 1; k < 64; k++) m = fmaxf(m, lg[k]);
        float sum = 0.0f;
#pragma unroll
        for (int k = 0; k < 64; k++) { lg[k] = __expf(lg[k] - m); sum += lg[k]; }
        float inv = 1.0f / sum;

        float4 xo[8];
#pragma unroll
        for (int i = 0; i < 8; i++) xo[i] = make_float4(0.f, 0.f, 0.f, 0.f);
#pragma unroll
        for (int k = 0; k < 64; k++) {
            float p = lg[k];
#pragma unroll
            for (int i = 0; i < 8; i++) {
                float4 vv = vch[k * 8 + i];
                xo[i].x += p * vv.x; xo[i].y += p * vv.y;
                xo[i].z += p * vv.z; xo[i].w += p * vv.w;
            }
        }
        __nv_bfloat16 xh[32], xl[32];
#pragma unroll
        for (int i = 0; i < 8; i++) {
            float vv[4] = {xo[i].x * inv, xo[i].y * inv, xo[i].z * inv, xo[i].w * inv};
#pragma unroll
            for (int cmp = 0; cmp < 4; cmp++) {
                __nv_bfloat16 hh = __float2bfloat16(vv[cmp]);
                xh[i*4+cmp] = hh;
                xl[i*4+cmp] = __float2bfloat16(vv[cmp] - __bfloat162float(hh));
            }
        }
        uint4* dsth = (uint4*)&g_xhi[n * CC + h * DD];
        uint4* dstl = (uint4*)&g_xlo[n * CC + h * DD];
#pragma unroll
        for (int i = 0; i < 4; i++) {
            dsth[i] = ((const uint4*)xh)[i];
            dstl[i] = ((const uint4*)xl)[i];
        }
    }
}

// ---------------- launcher ----------------
extern "C" void kernel_launch(void* const* d_in, const int* in_sizes, int n_in,
                              void* d_out, int out_size) {
    const float* X     = (const float*)d_in[0];
    const float* Ag    = (const float*)d_in[1];
    const float* wqkv  = (const float*)d_in[2];
    const float* wproj = (const float*)d_in[3];
    const float* bproj = (const float*)d_in[4];
    const float* cb    = (const float*)d_in[5];
    float* out = (float*)d_out;

    float *pq = nullptr;
    __nv_bfloat16 *pXhi, *pXlo, *pxhi, *pxlo, *pWqh, *pWql, *pWph, *pWpl;
    cudaGetSymbolAddress((void**)&pq, g_q);
    cudaGetSymbolAddress((void**)&pXhi, g_Xhi);
    cudaGetSymbolAddress((void**)&pXlo, g_Xlo);
    cudaGetSymbolAddress((void**)&pxhi, g_xhi);
    cudaGetSymbolAddress((void**)&pxlo, g_xlo);
    cudaGetSymbolAddress((void**)&pWqh, g_Wqt_hi);
    cudaGetSymbolAddress((void**)&pWql, g_Wqt_lo);
    cudaGetSymbolAddress((void**)&pWph, g_Wpt_hi);
    cudaGetSymbolAddress((void**)&pWpl, g_Wpt_lo);

    cudaFuncSetAttribute(gemm_bf16x3_mma,
                         cudaFuncAttributeMaxDynamicSharedMemorySize, GEMM_SMEM_BYTES);
    cudaFuncSetAttribute(pool_tc_kernel,
                         cudaFuncAttributeMaxDynamicSharedMemorySize, POOL_SMEM);
    cudaFuncSetAttribute(attn_kernel,
                         cudaFuncAttributeMaxDynamicSharedMemorySize,
                         ATT_SMEM_FLOATS * (int)sizeof(float));

    zero_kernel<<<(BB*KK*CC + 255) / 256, 256>>>();
    convertX_kernel<<<(BNTOT*CC) / (256*8), 256>>>(X);
    convertA_kernel<<<(BNTOT*KK) / (256*8), 256>>>(Ag);
    prepW_kernel<<<CC, 256>>>(wqkv, wproj);
    denom_kernel<<<BB * 16, 256>>>(Ag);
    bias_kernel<<<BNTOT / 256, 256>>>(Ag, cb);
    pool_tc_kernel<<<BB * 32, 256, POOL_SMEM>>>();
    kcvc_kernel<<<BB * KK, 256>>>(wqkv);
    {
        dim3 grid(BNTOT / 128, CC / 128);
        gemm_bf16x3_mma<<<grid, 256, GEMM_SMEM_BYTES>>>(pXhi, pXlo, pWqh, pWql, nullptr, pq);
    }
    attn_kernel<<<BB * (NN / 256), 256, ATT_SMEM_FLOATS * sizeof(float)>>>();
    {
        dim3 grid(BNTOT / 128, CC / 128);
        gemm_bf16x3_mma<<<grid, 256, GEMM_SMEM_BYTES>>>(pxhi, pxlo, pWph, pWpl, bproj, out);
    }
}

// round 7
// speedup vs baseline: 2.1654x; 1.3429x over previous
#include <cuda_runtime.h>
#include <cuda_bf16.h>
#include <cstdint>
#include <math.h>

#define BB 4
#define NN 16384
#define CC 256
#define HH 8
#define KK 64
#define DD 32
#define BNTOT (BB*NN)

// ---------------- scratch ----------------
__device__ float g_S[BB*KK*CC];
__device__ float g_denom[BB*KK];
__device__ float g_bias[BNTOT*KK];
__device__ __nv_bfloat16 g_Xhi[BNTOT*CC], g_Xlo[BNTOT*CC];
__device__ __nv_bfloat16 g_Ahi[BNTOT*KK], g_Alo[BNTOT*KK];
__device__ __nv_bfloat16 g_qhi[BNTOT*CC], g_qlo[BNTOT*CC];
__device__ __nv_bfloat16 g_xhi[BNTOT*CC], g_xlo[BNTOT*CC];
__device__ __nv_bfloat16 g_Wqt_hi[CC*CC], g_Wqt_lo[CC*CC];
__device__ __nv_bfloat16 g_Wpt_hi[CC*CC], g_Wpt_lo[CC*CC];
__device__ __nv_bfloat16 g_kchi[BB*HH*KK*DD], g_kclo[BB*HH*KK*DD];   // scaled, [b][h][cl][d]
__device__ __nv_bfloat16 g_vcThi[BB*HH*DD*KK], g_vcTlo[BB*HH*DD*KK]; // [b][h][d][cl]

// ---------------- helpers ----------------
__device__ __forceinline__ uint32_t smem_u32(const void* p) {
    uint32_t a;
    asm("{ .reg .u64 t; cvta.to.shared.u64 t, %1; cvt.u32.u64 %0, t; }" : "=r"(a) : "l"(p));
    return a;
}
#define CP16(dst, src) \
    asm volatile("cp.async.cg.shared.global [%0], [%1], 16;" :: "r"(dst), "l"(src))
#define CPCOMMIT() asm volatile("cp.async.commit_group;" ::: "memory")
#define CPWAIT(n)  asm volatile("cp.async.wait_group %0;" :: "n"(n) : "memory")

__device__ __forceinline__ void ldsm_x4(uint32_t* r, uint32_t addr) {
    asm volatile("ldmatrix.sync.aligned.m8n8.x4.shared.b16 {%0,%1,%2,%3}, [%4];"
                 : "=r"(r[0]), "=r"(r[1]), "=r"(r[2]), "=r"(r[3]) : "r"(addr));
}
__device__ __forceinline__ void ldsm_x4_t(uint32_t* r, uint32_t addr) {
    asm volatile("ldmatrix.sync.aligned.m8n8.x4.trans.shared.b16 {%0,%1,%2,%3}, [%4];"
                 : "=r"(r[0]), "=r"(r[1]), "=r"(r[2]), "=r"(r[3]) : "r"(addr));
}
__device__ __forceinline__ void mma_bf16(float* d, const uint32_t* a,
                                         uint32_t b0, uint32_t b1) {
    asm volatile(
        "mma.sync.aligned.m16n8k16.row.col.f32.bf16.bf16.f32 "
        "{%0,%1,%2,%3}, {%4,%5,%6,%7}, {%8,%9}, {%0,%1,%2,%3};"
        : "+f"(d[0]), "+f"(d[1]), "+f"(d[2]), "+f"(d[3])
        : "r"(a[0]), "r"(a[1]), "r"(a[2]), "r"(a[3]), "r"(b0), "r"(b1));
}
__device__ __forceinline__ void pack_split(float a, float b, uint32_t& hi, uint32_t& lo) {
    __nv_bfloat16 ah = __float2bfloat16(a), bh = __float2bfloat16(b);
    __nv_bfloat16 al = __float2bfloat16(a - __bfloat162float(ah));
    __nv_bfloat16 bl = __float2bfloat16(b - __bfloat162float(bh));
    __nv_bfloat162 hp; hp.x = ah; hp.y = bh;
    __nv_bfloat162 lp; lp.x = al; lp.y = bl;
    hi = *(uint32_t*)&hp; lo = *(uint32_t*)&lp;
}

// ---------------- zero accumulators ----------------
__global__ void zero_kernel() {
    int i = blockIdx.x * blockDim.x + threadIdx.x;
    if (i < BB*KK*CC) g_S[i] = 0.0f;
    if (i < BB*KK)    g_denom[i] = 0.0f;
}

// ---------------- splits ----------------
__global__ __launch_bounds__(256) void convertX_kernel(const float* __restrict__ X) {
    size_t i = ((size_t)blockIdx.x * 256 + threadIdx.x) * 8;
    float4 a = *(const float4*)(X + i);
    float4 b = *(const float4*)(X + i + 4);
    float v[8] = {a.x, a.y, a.z, a.w, b.x, b.y, b.z, b.w};
    __nv_bfloat16 h[8], l[8];
#pragma unroll
    for (int j = 0; j < 8; j++) {
        h[j] = __float2bfloat16(v[j]);
        l[j] = __float2bfloat16(v[j] - __bfloat162float(h[j]));
    }
    *(uint4*)&g_Xhi[i] = *(const uint4*)h;
    *(uint4*)&g_Xlo[i] = *(const uint4*)l;
}
__global__ __launch_bounds__(256) void convertA_kernel(const float* __restrict__ Ag) {
    size_t i = ((size_t)blockIdx.x * 256 + threadIdx.x) * 8;
    float4 a = *(const float4*)(Ag + i);
    float4 b = *(const float4*)(Ag + i + 4);
    float v[8] = {a.x, a.y, a.z, a.w, b.x, b.y, b.z, b.w};
    __nv_bfloat16 h[8], l[8];
#pragma unroll
    for (int j = 0; j < 8; j++) {
        h[j] = __float2bfloat16(v[j]);
        l[j] = __float2bfloat16(v[j] - __bfloat162float(h[j]));
    }
    *(uint4*)&g_Ahi[i] = *(const uint4*)h;
    *(uint4*)&g_Alo[i] = *(const uint4*)l;
}

// ---------------- transposed bf16 hi/lo weights ----------------
__global__ __launch_bounds__(256) void prepW_kernel(const float* __restrict__ wqkv,
                                                    const float* __restrict__ wproj) {
    int n = blockIdx.x, k = threadIdx.x;
    float wq = wqkv[k * (3*CC) + n];
    float wp = wproj[k * CC + n];
    __nv_bfloat16 qh = __float2bfloat16(wq);
    __nv_bfloat16 ph = __float2bfloat16(wp);
    int o = n * CC + k;
    g_Wqt_hi[o] = qh;
    g_Wqt_lo[o] = __float2bfloat16(wq - __bfloat162float(qh));
    g_Wpt_hi[o] = ph;
    g_Wpt_lo[o] = __float2bfloat16(wp - __bfloat162float(ph));
}

// ---------------- exact fp32 denom ----------------
__global__ __launch_bounds__(256) void denom_kernel(const float* __restrict__ Ag) {
    __shared__ float red[4][64];
    int blk = blockIdx.x;
    int b = blk >> 4, seg = blk & 15;
    int k = threadIdx.x & 63, rr = threadIdx.x >> 6;
    float s = 0.0f;
    size_t base = (size_t)b * NN + seg * 1024;
#pragma unroll 4
    for (int i = 0; i < 256; i++) s += Ag[(base + rr + i * 4) * KK + k];
    red[rr][k] = s;
    __syncthreads();
    if (threadIdx.x < 64)
        atomicAdd(&g_denom[b * KK + threadIdx.x],
                  red[0][threadIdx.x] + red[1][threadIdx.x] +
                  red[2][threadIdx.x] + red[3][threadIdx.x]);
}

// ---------------- bias = A @ cluster_bias ----------------
__global__ __launch_bounds__(256) void bias_kernel(const float* __restrict__ Ag,
                                                   const float* __restrict__ cb) {
    __shared__ float cb_s[KK*KK];
    int tid = threadIdx.x;
    {
        const float4* cb4 = (const float4*)cb;
        float4* cbs4 = (float4*)cb_s;
        for (int i = tid; i < KK*KK/4; i += 256) cbs4[i] = cb4[i];
    }
    __syncthreads();
    size_t n = (size_t)blockIdx.x * 256 + tid;
    float biasr[64];
#pragma unroll
    for (int l = 0; l < 64; l++) biasr[l] = 0.0f;
    const float4* arow = (const float4*)(Ag + n * KK);
#pragma unroll
    for (int k4 = 0; k4 < 16; k4++) {
        float4 a4 = arow[k4];
        float avv[4] = {a4.x, a4.y, a4.z, a4.w};
#pragma unroll
        for (int kk = 0; kk < 4; kk++) {
            const float4* cbr = (const float4*)(cb_s + (k4 * 4 + kk) * 64);
#pragma unroll
            for (int l4 = 0; l4 < 16; l4++) {
                float4 c4 = cbr[l4];
                biasr[l4*4+0] += avv[kk] * c4.x;
                biasr[l4*4+1] += avv[kk] * c4.y;
                biasr[l4*4+2] += avv[kk] * c4.z;
                biasr[l4*4+3] += avv[kk] * c4.w;
            }
        }
    }
    float4* dst = (float4*)(g_bias + n * KK);
#pragma unroll
    for (int l4 = 0; l4 < 16; l4++)
        dst[l4] = make_float4(biasr[l4*4], biasr[l4*4+1], biasr[l4*4+2], biasr[l4*4+3]);
}

// ---------------- tensor-core pooling (unchanged) ----------------
#define PX_ST 264
#define PA_ST 72
#define PX_SIZE (64*PX_ST)
#define PA_SIZE (64*PA_ST)
#define POOL_SMEM ((3*PX_SIZE + 3*PA_SIZE)*2)
__global__ __launch_bounds__(256, 1) void pool_tc_kernel() {
    extern __shared__ __nv_bfloat16 ps[];
    uint32_t sb = smem_u32(ps);
    int tid = threadIdx.x, lane = tid & 31, w = tid >> 5;
    int wm = w >> 2, wn = w & 3;
    int b = blockIdx.x >> 5;
    int nbase = (blockIdx.x & 31) * 512;
    const __nv_bfloat16* Asrc[3] = {g_Ahi, g_Ahi, g_Alo};
    const __nv_bfloat16* Xsrc[3] = {g_Xhi, g_Xlo, g_Xhi};

    float acc[2][8][4];
#pragma unroll
    for (int i = 0; i < 2; i++)
#pragma unroll
        for (int j = 0; j < 8; j++)
#pragma unroll
            for (int r = 0; r < 4; r++) acc[i][j][r] = 0.0f;

    auto issue = [&](int c) {
        int s = c >> 3, kc_ = c & 7, buf = c % 3;
        size_t grow0 = (size_t)b * NN + nbase + kc_ * 64;
#pragma unroll
        for (int i = 0; i < 8; i++) {
            int idx = tid + i * 256;
            int row = idx >> 5, ch = idx & 31;
            CP16(sb + (uint32_t)(buf * PX_SIZE + row * PX_ST + ch * 8) * 2,
                 Xsrc[s] + (grow0 + row) * CC + ch * 8);
        }
#pragma unroll
        for (int i = 0; i < 2; i++) {
            int idx = tid + i * 256;
            int row = idx >> 3, ch = idx & 7;
            CP16(sb + (uint32_t)(3 * PX_SIZE + buf * PA_SIZE + row * PA_ST + ch * 8) * 2,
                 Asrc[s] + (grow0 + row) * KK + ch * 8);
        }
        CPCOMMIT();
    };

    issue(0); issue(1);
#pragma unroll 1
    for (int c = 0; c < 24; c++) {
        if (c < 22) { CPWAIT(1); } else { CPWAIT(0); }
        __syncthreads();
        if (c + 2 < 24) issue(c + 2);
        int buf = c % 3;
        uint32_t xb = sb + (uint32_t)(buf * PX_SIZE) * 2;
        uint32_t ab = sb + (uint32_t)(3 * PX_SIZE + buf * PA_SIZE) * 2;
#pragma unroll
        for (int kt = 0; kt < 4; kt++) {
            uint32_t af[2][4];
#pragma unroll
            for (int mt = 0; mt < 2; mt++) {
                uint32_t r[4];
                ldsm_x4_t(r, ab + (uint32_t)((kt * 16 + (lane & 15)) * PA_ST +
                                             wm * 32 + mt * 16 + (lane >> 4) * 8) * 2);
                af[mt][0] = r[0]; af[mt][1] = r[2]; af[mt][2] = r[1]; af[mt][3] = r[3];
            }
#pragma unroll
            for (int nb = 0; nb < 4; nb++) {
                uint32_t bfr[4];
                ldsm_x4_t(bfr, xb + (uint32_t)((kt * 16 + (lane & 15)) * PX_ST +
                                               wn * 64 + nb * 16 + (lane >> 4) * 8) * 2);
#pragma unroll
                for (int mt = 0; mt < 2; mt++) {
                    mma_bf16(acc[mt][nb*2],   af[mt], bfr[0], bfr[1]);
                    mma_bf16(acc[mt][nb*2+1], af[mt], bfr[2], bfr[3]);
                }
            }
        }
    }
#pragma unroll
    for (int mt = 0; mt < 2; mt++)
#pragma unroll
        for (int nt = 0; nt < 8; nt++) {
            int cl = wm * 32 + mt * 16 + (lane >> 2);
            int col = wn * 64 + nt * 8 + 2 * (lane & 3);
            float* d0 = &g_S[(b * KK + cl) * CC + col];
            atomicAdd(d0,     acc[mt][nt][0]);
            atomicAdd(d0 + 1, acc[mt][nt][1]);
            float* d1 = &g_S[(b * KK + cl + 8) * CC + col];
            atomicAdd(d1,     acc[mt][nt][2]);
            atomicAdd(d1 + 1, acc[mt][nt][3]);
        }
}

// ---------------- kc/vc from S -> scaled bf16 splits + transposed vc ----------------
__global__ __launch_bounds__(256) void kcvc_kernel(const float* __restrict__ wqkv) {
    int bk = blockIdx.x;
    int b = bk >> 6;
    int k = bk & 63;
    int t = threadIdx.x;
    __shared__ float s_row[CC];
    s_row[t] = g_S[bk * CC + t];
    __syncthreads();
    float inv = 1.0f / (g_denom[bk] + 1e-8f);
    float ak = 0.0f, av = 0.0f;
#pragma unroll 8
    for (int c = 0; c < CC; c++) {
        float s = s_row[c];
        ak += s * wqkv[c * (3*CC) + CC  + t];
        av += s * wqkv[c * (3*CC) + 2*CC + t];
    }
    int h = t >> 5, dd = t & 31;
    const float SC = 0.17677669529663689f;
    float kcv = ak * inv * SC;      // fold attention scale into kc
    float vcv = av * inv;
    size_t ok = ((size_t)(b * HH + h) * KK + k) * DD + dd;
    size_t ov = ((size_t)(b * HH + h) * DD + dd) * KK + k;
    __nv_bfloat16 kh = __float2bfloat16(kcv);
    __nv_bfloat16 vh = __float2bfloat16(vcv);
    g_kchi[ok] = kh;  g_kclo[ok] = __float2bfloat16(kcv - __bfloat162float(kh));
    g_vcThi[ov] = vh; g_vcTlo[ov] = __float2bfloat16(vcv - __bfloat162float(vh));
}

// ---------------- HMMA bf16 3-split GEMM: fp32 out (+bias) OR bf16 split out ----------
#define AST 40
#define STAGE_ELE (128 * AST)
#define GEMM_SMEM_BYTES (2 * 3 * STAGE_ELE * 2)
__global__ __launch_bounds__(256, 2) void gemm_bf16x3_mma(
    const __nv_bfloat16* __restrict__ Ahi, const __nv_bfloat16* __restrict__ Alo,
    const __nv_bfloat16* __restrict__ Whi, const __nv_bfloat16* __restrict__ Wlo,
    const float* __restrict__ bias, float* __restrict__ Cout,
    __nv_bfloat16* __restrict__ Ohi, __nv_bfloat16* __restrict__ Olo) {
    extern __shared__ __nv_bfloat16 smemb[];
    __nv_bfloat16* As = smemb;
    __nv_bfloat16* Bs = smemb + 3 * STAGE_ELE;
    uint32_t a_sm = smem_u32(As);
    uint32_t b_sm = smem_u32(Bs);

    int tid = threadIdx.x;
    int lane = tid & 31, w = tid >> 5;
    int wr = w >> 2, wc = w & 3;
    size_t mbase = (size_t)blockIdx.x * 128;
    int nbase = blockIdx.y * 128;

    const __nv_bfloat16* Asp[3] = {Ahi, Ahi, Alo};
    const __nv_bfloat16* Wsp[3] = {Whi, Wlo, Whi};

    int ldrow = tid >> 2;
    int ldwd  = tid & 3;

    float acc[4][4][4];
#pragma unroll
    for (int i = 0; i < 4; i++)
#pragma unroll
        for (int j = 0; j < 4; j++)
#pragma unroll
            for (int r = 0; r < 4; r++) acc[i][j][r] = 0.0f;

    auto issue = [&](int c) {
        int s = c >> 3;
        int ko = (c & 7) * 32;
        const __nv_bfloat16* Ap = Asp[s];
        const __nv_bfloat16* Wp = Wsp[s];
        uint32_t sa = a_sm + (uint32_t)((c % 3) * STAGE_ELE) * 2;
        uint32_t sb = b_sm + (uint32_t)((c % 3) * STAGE_ELE) * 2;
#pragma unroll
        for (int t = 0; t < 2; t++) {
            int row = ldrow + t * 64;
            CP16(sa + (uint32_t)(row * AST + ldwd * 8) * 2,
                 Ap + (mbase + row) * CC + ko + ldwd * 8);
            CP16(sb + (uint32_t)(row * AST + ldwd * 8) * 2,
                 Wp + (size_t)(nbase + row) * CC + ko + ldwd * 8);
        }
        CPCOMMIT();
    };

    int arow = (lane & 7) + 8 * ((lane >> 3) & 1);
    int akw  = (lane >> 4) * 8;
    int brow = (lane & 7) + 8 * ((lane >> 4) & 1);
    int bkw  = ((lane >> 3) & 1) * 8;

    auto compute = [&](int stage) {
        uint32_t sa = a_sm + (uint32_t)(stage * STAGE_ELE) * 2;
        uint32_t sb = b_sm + (uint32_t)(stage * STAGE_ELE) * 2;
#pragma unroll
        for (int ks = 0; ks < 32; ks += 16) {
            uint32_t afr[4][4];
#pragma unroll
            for (int mt = 0; mt < 4; mt++)
                ldsm_x4(afr[mt], sa + (uint32_t)(((wr * 64 + mt * 16 + arow) * AST) + ks + akw) * 2);
            uint32_t bfr[2][4];
#pragma unroll
            for (int nt2 = 0; nt2 < 2; nt2++)
                ldsm_x4(bfr[nt2], sb + (uint32_t)(((wc * 32 + nt2 * 16 + brow) * AST) + ks + bkw) * 2);
#pragma unroll
            for (int mt = 0; mt < 4; mt++)
#pragma unroll
                for (int nt = 0; nt < 4; nt++)
                    mma_bf16(acc[mt][nt], afr[mt],
                             bfr[nt >> 1][(nt & 1) * 2],
                             bfr[nt >> 1][(nt & 1) * 2 + 1]);
        }
    };

    issue(0);
    issue(1);
#pragma unroll 1
    for (int c = 0; c < 24; c++) {
        if (c < 22) { CPWAIT(1); } else { CPWAIT(0); }
        __syncthreads();
        if (c + 2 < 24) issue(c + 2);
        compute(c % 3);
    }

    int g = lane >> 2, ti = lane & 3;
#pragma unroll
    for (int mt = 0; mt < 4; mt++) {
#pragma unroll
        for (int nt = 0; nt < 4; nt++) {
            size_t row = mbase + wr * 64 + mt * 16 + g;
            int col = nbase + wc * 32 + nt * 8 + ti * 2;
            if (Cout) {
                float bx = 0.0f, by = 0.0f;
                if (bias) { bx = bias[col]; by = bias[col + 1]; }
                float2 v0, v1;
                v0.x = acc[mt][nt][0] + bx; v0.y = acc[mt][nt][1] + by;
                v1.x = acc[mt][nt][2] + bx; v1.y = acc[mt][nt][3] + by;
                *(float2*)&Cout[row * CC + col] = v0;
                *(float2*)&Cout[(row + 8) * CC + col] = v1;
            } else {
                uint32_t h0, l0, h1, l1;
                pack_split(acc[mt][nt][0], acc[mt][nt][1], h0, l0);
                pack_split(acc[mt][nt][2], acc[mt][nt][3], h1, l1);
                *(uint32_t*)&Ohi[row * CC + col] = h0;
                *(uint32_t*)&Olo[row * CC + col] = l0;
                *(uint32_t*)&Ohi[(row + 8) * CC + col] = h1;
                *(uint32_t*)&Olo[(row + 8) * CC + col] = l1;
            }
        }
    }
}

// ---------------- tensor-core attention ----------------
// grid 512 CTAs x 128 tokens; 8 warps = m16 tile each. kc/vcT double-buffered per head.
#define ATT_BUF_BYTES 19456
#define ATT_SMEM_BYTES (2 * ATT_BUF_BYTES)
__global__ __launch_bounds__(256) void attn_tc_kernel() {
    extern __shared__ __nv_bfloat16 smn[];
    uint32_t sb = smem_u32(smn);
    int tid = threadIdx.x, lane = tid & 31, w = tid >> 5;
    size_t tok0 = (size_t)blockIdx.x * 128;
    int b = blockIdx.x >> 7;
    int r = lane >> 2, c = lane & 3;
    size_t trow0 = tok0 + (size_t)w * 16 + r;
    size_t trow1 = trow0 + 8;

    const uint32_t KHI = 0, KLO = 5120, VHI = 10240, VLO = 14848;  // byte offsets in buf

    auto issue_head = [&](int h) {
        uint32_t bo = (uint32_t)(h & 1) * ATT_BUF_BYTES;
        {   // kc tiles: 64 rows x 32 bf16, stride 40 elems
            int rr = tid >> 2, cc = tid & 3;
            size_t src = ((size_t)(b * HH + h) * KK + rr) * DD + cc * 8;
            uint32_t d = (uint32_t)(rr * 40 + cc * 8) * 2;
            CP16(sb + bo + KHI + d, g_kchi + src);
            CP16(sb + bo + KLO + d, g_kclo + src);
        }
        {   // vcT tiles: 32 rows x 64 bf16, stride 72 elems
            int rr = tid >> 3, cc = tid & 7;
            size_t src = ((size_t)(b * HH + h) * DD + rr) * KK + cc * 8;
            uint32_t d = (uint32_t)(rr * 72 + cc * 8) * 2;
            CP16(sb + bo + VHI + d, g_vcThi + src);
            CP16(sb + bo + VLO + d, g_vcTlo + src);
        }
        CPCOMMIT();
    };
    issue_head(0);

    // bias fragments, loaded once (cluster = 8*tile + 2c)
    float Lbias[8][4];
#pragma unroll
    for (int t = 0; t < 8; t++) {
        float2 b0 = *(const float2*)(g_bias + trow0 * KK + t * 8 + c * 2);
        float2 b1 = *(const float2*)(g_bias + trow1 * KK + t * 8 + c * 2);
        Lbias[t][0] = b0.x; Lbias[t][1] = b0.y;
        Lbias[t][2] = b1.x; Lbias[t][3] = b1.y;
    }

    int brow = (lane & 7) + 8 * ((lane >> 4) & 1);
    int bkw  = ((lane >> 3) & 1) * 8;

#pragma unroll 1
    for (int h = 0; h < HH; h++) {
        CPWAIT(0);
        __syncthreads();
        if (h + 1 < HH) issue_head(h + 1);
        uint32_t bo = (uint32_t)(h & 1) * ATT_BUF_BYTES;

        // Q fragments direct from global (a0={r,2c},a1={r+8,2c},a2={r,2c+8},a3={r+8,2c+8})
        uint32_t qhi[2][4], qlo[2][4];
#pragma unroll
        for (int ks = 0; ks < 2; ks++) {
            size_t col = (size_t)h * DD + ks * 16 + c * 2;
            qhi[ks][0] = *(const uint32_t*)(g_qhi + trow0 * CC + col);
            qhi[ks][1] = *(const uint32_t*)(g_qhi + trow1 * CC + col);
            qhi[ks][2] = *(const uint32_t*)(g_qhi + trow0 * CC + col + 8);
            qhi[ks][3] = *(const uint32_t*)(g_qhi + trow1 * CC + col + 8);
            qlo[ks][0] = *(const uint32_t*)(g_qlo + trow0 * CC + col);
            qlo[ks][1] = *(const uint32_t*)(g_qlo + trow1 * CC + col);
            qlo[ks][2] = *(const uint32_t*)(g_qlo + trow0 * CC + col + 8);
            qlo[ks][3] = *(const uint32_t*)(g_qlo + trow1 * CC + col + 8);
        }

        // logits = bias + Q·kc^T (3-split)
        float L[8][4];
#pragma unroll
        for (int t = 0; t < 8; t++)
#pragma unroll
            for (int v = 0; v < 4; v++) L[t][v] = Lbias[t][v];
#pragma unroll
        for (int g2 = 0; g2 < 4; g2++) {
#pragma unroll
            for (int ks = 0; ks < 2; ks++) {
                uint32_t bh[4], bl[4];
                uint32_t ad = (uint32_t)((g2 * 16 + brow) * 40 + ks * 16 + bkw) * 2;
                ldsm_x4(bh, sb + bo + KHI + ad);
                ldsm_x4(bl, sb + bo + KLO + ad);
                mma_bf16(L[2*g2],   qhi[ks], bh[0], bh[1]);
                mma_bf16(L[2*g2],   qhi[ks], bl[0], bl[1]);
                mma_bf16(L[2*g2],   qlo[ks], bh[0], bh[1]);
                mma_bf16(L[2*g2+1], qhi[ks], bh[2], bh[3]);
                mma_bf16(L[2*g2+1], qhi[ks], bl[2], bl[3]);
                mma_bf16(L[2*g2+1], qlo[ks], bh[2], bh[3]);
            }
        }

        // softmax over 64 clusters per row (rows r, r+8); quad shuffles
        float m0 = -1e30f, m1 = -1e30f;
#pragma unroll
        for (int t = 0; t < 8; t++) {
            m0 = fmaxf(m0, fmaxf(L[t][0], L[t][1]));
            m1 = fmaxf(m1, fmaxf(L[t][2], L[t][3]));
        }
        m0 = fmaxf(m0, __shfl_xor_sync(0xffffffffu, m0, 1));
        m0 = fmaxf(m0, __shfl_xor_sync(0xffffffffu, m0, 2));
        m1 = fmaxf(m1, __shfl_xor_sync(0xffffffffu, m1, 1));
        m1 = fmaxf(m1, __shfl_xor_sync(0xffffffffu, m1, 2));
        float s0 = 0.0f, s1 = 0.0f;
#pragma unroll
        for (int t = 0; t < 8; t++) {
            L[t][0] = __expf(L[t][0] - m0); s0 += L[t][0];
            L[t][1] = __expf(L[t][1] - m0); s0 += L[t][1];
            L[t][2] = __expf(L[t][2] - m1); s1 += L[t][2];
            L[t][3] = __expf(L[t][3] - m1); s1 += L[t][3];
        }
        s0 += __shfl_xor_sync(0xffffffffu, s0, 1);
        s0 += __shfl_xor_sync(0xffffffffu, s0, 2);
        s1 += __shfl_xor_sync(0xffffffffu, s1, 1);
        s1 += __shfl_xor_sync(0xffffffffu, s1, 2);
        float inv0 = 1.0f / s0, inv1 = 1.0f / s1;

        // PV: out[16][32] = P·vcT^T, P split hi/lo in-register
        float O[4][4];
#pragma unroll
        for (int t = 0; t < 4; t++)
#pragma unroll
            for (int v = 0; v < 4; v++) O[t][v] = 0.0f;
#pragma unroll
        for (int kc_ = 0; kc_ < 4; kc_++) {
            // A fragment from P tiles 2kc_, 2kc_+1
            uint32_t ahi[4], alo[4];
            pack_split(L[2*kc_][0]*inv0,   L[2*kc_][1]*inv0,   ahi[0], alo[0]);
            pack_split(L[2*kc_][2]*inv1,   L[2*kc_][3]*inv1,   ahi[1], alo[1]);
            pack_split(L[2*kc_+1][0]*inv0, L[2*kc_+1][1]*inv0, ahi[2], alo[2]);
            pack_split(L[2*kc_+1][2]*inv1, L[2*kc_+1][3]*inv1, ahi[3], alo[3]);
#pragma unroll
            for (int g2 = 0; g2 < 2; g2++) {
                uint32_t bh[4], bl[4];
                uint32_t ad = (uint32_t)((g2 * 16 + brow) * 72 + kc_ * 16 + bkw) * 2;
                ldsm_x4(bh, sb + bo + VHI + ad);
                ldsm_x4(bl, sb + bo + VLO + ad);
                mma_bf16(O[2*g2],   ahi, bh[0], bh[1]);
                mma_bf16(O[2*g2],   ahi, bl[0], bl[1]);
                mma_bf16(O[2*g2],   alo, bh[0], bh[1]);
                mma_bf16(O[2*g2+1], ahi, bh[2], bh[3]);
                mma_bf16(O[2*g2+1], ahi, bl[2], bl[3]);
                mma_bf16(O[2*g2+1], alo, bh[2], bh[3]);
            }
        }

        // store split x
#pragma unroll
        for (int nt = 0; nt < 4; nt++) {
            size_t col = (size_t)h * DD + nt * 8 + c * 2;
            uint32_t h0, l0, h1, l1;
            pack_split(O[nt][0], O[nt][1], h0, l0);
            pack_split(O[nt][2], O[nt][3], h1, l1);
            *(uint32_t*)&g_xhi[trow0 * CC + col] = h0;
            *(uint32_t*)&g_xlo[trow0 * CC + col] = l0;
            *(uint32_t*)&g_xhi[trow1 * CC + col] = h1;
            *(uint32_t*)&g_xlo[trow1 * CC + col] = l1;
        }
    }
}

// ---------------- launcher ----------------
extern "C" void kernel_launch(void* const* d_in, const int* in_sizes, int n_in,
                              void* d_out, int out_size) {
    const float* X     = (const float*)d_in[0];
    const float* Ag    = (const float*)d_in[1];
    const float* wqkv  = (const float*)d_in[2];
    const float* wproj = (const float*)d_in[3];
    const float* bproj = (const float*)d_in[4];
    const float* cb    = (const float*)d_in[5];
    float* out = (float*)d_out;

    __nv_bfloat16 *pXhi, *pXlo, *pqhi, *pqlo, *pxhi, *pxlo, *pWqh, *pWql, *pWph, *pWpl;
    cudaGetSymbolAddress((void**)&pXhi, g_Xhi);
    cudaGetSymbolAddress((void**)&pXlo, g_Xlo);
    cudaGetSymbolAddress((void**)&pqhi, g_qhi);
    cudaGetSymbolAddress((void**)&pqlo, g_qlo);
    cudaGetSymbolAddress((void**)&pxhi, g_xhi);
    cudaGetSymbolAddress((void**)&pxlo, g_xlo);
    cudaGetSymbolAddress((void**)&pWqh, g_Wqt_hi);
    cudaGetSymbolAddress((void**)&pWql, g_Wqt_lo);
    cudaGetSymbolAddress((void**)&pWph, g_Wpt_hi);
    cudaGetSymbolAddress((void**)&pWpl, g_Wpt_lo);

    cudaFuncSetAttribute(gemm_bf16x3_mma,
                         cudaFuncAttributeMaxDynamicSharedMemorySize, GEMM_SMEM_BYTES);
    cudaFuncSetAttribute(pool_tc_kernel,
                         cudaFuncAttributeMaxDynamicSharedMemorySize, POOL_SMEM);
    cudaFuncSetAttribute(attn_tc_kernel,
                         cudaFuncAttributeMaxDynamicSharedMemorySize, ATT_SMEM_BYTES);

    zero_kernel<<<(BB*KK*CC + 255) / 256, 256>>>();
    convertX_kernel<<<(BNTOT*CC) / (256*8), 256>>>(X);
    convertA_kernel<<<(BNTOT*KK) / (256*8), 256>>>(Ag);
    prepW_kernel<<<CC, 256>>>(wqkv, wproj);
    denom_kernel<<<BB * 16, 256>>>(Ag);
    bias_kernel<<<BNTOT / 256, 256>>>(Ag, cb);
    pool_tc_kernel<<<BB * 32, 256, POOL_SMEM>>>();
    kcvc_kernel<<<BB * KK, 256>>>(wqkv);
    {   // Q = X @ Wq, emitted as bf16 hi/lo splits
        dim3 grid(BNTOT / 128, CC / 128);
        gemm_bf16x3_mma<<<grid, 256, GEMM_SMEM_BYTES>>>(pXhi, pXlo, pWqh, pWql,
                                                        nullptr, nullptr, pqhi, pqlo);
    }
    attn_tc_kernel<<<BNTOT / 128, 256, ATT_SMEM_BYTES>>>();
    {   // out = x @ Wproj + b
        dim3 grid(BNTOT / 128, CC / 128);
        gemm_bf16x3_mma<<<grid, 256, GEMM_SMEM_BYTES>>>(pxhi, pxlo, pWph, pWpl,
                                                        bproj, out, nullptr, nullptr);
    }
}